// round 14
// baseline (speedup 1.0000x reference)
#include <cuda_runtime.h>
#include <cuda_fp16.h>
#include <cstdint>

#define BB   2
#define LL   2048
#define KNN  48
#define ED   128
#define NCH  13            // 13 K-chunks of 32 fp32 cols = K=416

#define ASTR 20            // A smem row stride in u32 (16 half2 + 4 pad)
#define WSTR 132           // W smem row stride in u32 (128 + 4 pad)
#define AWRD (96 * ASTR)   // words per A stage = 1920
#define WWRD (16 * WSTR)   // words per W stage = 2112 (16 k-pair rows)
#define DSMW (2 * AWRD + 4 * WWRD)   // 12288 words = 49152 B

// scratch (allocation-free rule: __device__ globals)
__device__ float    g_atoms[BB * LL * 15];
__device__ float4   g_ca[BB * LL];    // packed (Ca.xyz, mask) for topk
__device__ int      g_eidx[BB * LL * KNN];
__device__ unsigned g_Wh[208 * ED];   // W as half2 k-pairs: [k/2][n]

__device__ __forceinline__ unsigned smem_u32(const void* p) {
    unsigned a;
    asm("{ .reg .u64 t; cvta.to.shared.u64 t, %1; cvt.u32.u64 %0, t; }"
        : "=r"(a) : "l"(p));
    return a;
}
__device__ __forceinline__ void cp16(unsigned dst, const void* src) {
    asm volatile("cp.async.cg.shared.global [%0], [%1], 16;" :: "r"(dst), "l"(src));
}
__device__ __forceinline__ void cp_commit() {
    asm volatile("cp.async.commit_group;" ::: "memory");
}
__device__ __forceinline__ void cp_wait2() {
    asm volatile("cp.async.wait_group 2;" ::: "memory");
}
__device__ __forceinline__ unsigned packh2(float a, float b) {
    __half2 h = __floats2half2_rn(a, b);
    return *(unsigned*)&h;
}
__device__ __forceinline__ void ldmA(unsigned* a, unsigned addr) {
    asm volatile(
        "ldmatrix.sync.aligned.m8n8.x4.shared.b16 {%0,%1,%2,%3}, [%4];"
        : "=r"(a[0]), "=r"(a[1]), "=r"(a[2]), "=r"(a[3]) : "r"(addr));
}

#define MMA_F16(d, a, b)                                                      \
    asm volatile(                                                             \
        "mma.sync.aligned.m16n8k16.row.col.f32.f16.f16.f32 "                  \
        "{%0,%1,%2,%3}, {%4,%5,%6,%7}, {%8,%9}, {%0,%1,%2,%3};"               \
        : "+f"(d[0]), "+f"(d[1]), "+f"(d[2]), "+f"(d[3])                      \
        : "r"(a[0]), "r"(a[1]), "r"(a[2]), "r"(a[3]), "r"(b[0]), "r"(b[1]))

// ---------------------------------------------------------------------------
// Kernel 0 (merged prep): blocks 0..15 build atoms + packed (Ca,mask);
// blocks 16+ pack W into half2 k-pairs g_Wh[kk][n] (k-major rows).
// ---------------------------------------------------------------------------
__global__ void prep_kernel(const float* __restrict__ X,
                            const float* __restrict__ mask,
                            const float* __restrict__ W) {
    if (blockIdx.x < 16) {
        int idx = blockIdx.x * 256 + threadIdx.x;
        if (idx >= BB * LL) return;
        const float* x = X + (size_t)idx * 12;
        float Nx = x[0],  Ny = x[1],  Nz = x[2];
        float Cax = x[3], Cay = x[4], Caz = x[5];
        float Cx = x[6],  Cy = x[7],  Cz = x[8];
        float Ox = x[9],  Oy = x[10], Oz = x[11];

        float bx = Cax - Nx,  by = Cay - Ny,  bz = Caz - Nz;
        float cx = Cx - Cax,  cy = Cy - Cay,  cz = Cz - Caz;
        float ax = by * cz - bz * cy;
        float ay = bz * cx - bx * cz;
        float az = bx * cy - by * cx;
        float Cbx = -0.58273431f * ax + 0.56802827f * bx - 0.54067466f * cx + Cax;
        float Cby = -0.58273431f * ay + 0.56802827f * by - 0.54067466f * cy + Cay;
        float Cbz = -0.58273431f * az + 0.56802827f * bz - 0.54067466f * cz + Caz;

        float* o = g_atoms + (size_t)idx * 15;
        o[0]  = Cax; o[1]  = Cay; o[2]  = Caz;
        o[3]  = Nx;  o[4]  = Ny;  o[5]  = Nz;
        o[6]  = Cx;  o[7]  = Cy;  o[8]  = Cz;
        o[9]  = Ox;  o[10] = Oy;  o[11] = Oz;
        o[12] = Cbx; o[13] = Cby; o[14] = Cbz;
        g_ca[idx] = make_float4(Cax, Cay, Caz, mask[idx]);
    } else {
        int idx = (blockIdx.x - 16) * 256 + threadIdx.x;
        if (idx >= 208 * ED) return;
        int kk = idx / ED, n = idx % ED;
        g_Wh[idx] = packh2(W[(2 * kk) * ED + n], W[(2 * kk + 1) * ED + n]);
    }
}

// ---------------------------------------------------------------------------
// Radix-select helper (warp 0 scans hist[256] for pivot crossing thr)
// ---------------------------------------------------------------------------
__device__ __forceinline__ void scan_pivot(const unsigned* hist, unsigned thr,
                                           unsigned* s_pivot, unsigned* s_base,
                                           int tid) {
    if (tid < 32) {
        unsigned v[8], pre[8], s = 0;
#pragma unroll
        for (int j = 0; j < 8; j++) { v[j] = hist[tid * 8 + j]; pre[j] = s; s += v[j]; }
        unsigned tot = s, x = tot;
#pragma unroll
        for (int off = 1; off < 32; off <<= 1) {
            unsigned y = __shfl_up_sync(0xffffffffu, x, off);
            if (tid >= off) x += y;
        }
        unsigned ex = x - tot;
        if (ex < thr && ex + tot >= thr) {
#pragma unroll
            for (int j = 0; j < 8; j++) {
                unsigned cb = ex + pre[j];
                if (cb < thr && cb + v[j] >= thr) { *s_pivot = tid * 8 + j; *s_base = cb; }
            }
        }
    }
}

// ---------------------------------------------------------------------------
// Kernel 2: top-K, 2 rows per block. Both rows' squared-distance keys are
// built in ONE pass over j (each coord loaded once as float4, serving both
// rows), held in registers; coords smem then re-aliased as cand buffers for
// two sequential selection phases. Selection = smallest-64 radix superset ->
// exact sqrt on 64 finalists -> exact bitonic sort (bit-identical E_idx).
// ---------------------------------------------------------------------------
__global__ void __launch_bounds__(256) topk_kernel(float* __restrict__ outI) {
    __shared__ __align__(16) char sbuf[32768];
    float4* c4s = (float4*)sbuf;                                      // 32KB
    unsigned long long* cand1 = (unsigned long long*)sbuf;            // 16KB
    unsigned long long* cand2 = (unsigned long long*)(sbuf + 16384);  // 16KB
    __shared__ unsigned hist[256];
    __shared__ unsigned long long win[64];
    __shared__ unsigned s_nwin, s_nc1, s_nc2, s_pivot, s_base;
    __shared__ float wmaxs[8];
    __shared__ float s_dmx[2];

    const unsigned INF_BITS = 0x7F800000u;

    int b   = blockIdx.x >> 10;
    int i0  = (blockIdx.x & 1023) * 2;
    int tid = threadIdx.x;
    int lane = tid & 31, wid = tid >> 5;

    for (int t = tid; t < LL; t += 256)
        c4s[t] = g_ca[b * LL + t];
    __syncthreads();

    float4 p0 = c4s[i0], p1 = c4s[i0 + 1];
    unsigned long long k0[8], k1[8];
    float smax0 = -1.0f, smax1 = -1.0f;
#pragma unroll
    for (int u = 0; u < 8; u++) {
        int j = tid * 8 + u;
        float4 v = c4s[j];
        // exact fp32 op order, no fma-contraction (matches XLA up to sqrt)
        float dx0 = __fsub_rn(v.x, p0.x);
        float dy0 = __fsub_rn(v.y, p0.y);
        float dz0 = __fsub_rn(v.z, p0.z);
        float s0  = __fadd_rn(__fadd_rn(__fmul_rn(dx0, dx0), __fmul_rn(dy0, dy0)),
                              __fmul_rn(dz0, dz0));
        float dx1 = __fsub_rn(v.x, p1.x);
        float dy1 = __fsub_rn(v.y, p1.y);
        float dz1 = __fsub_rn(v.z, p1.z);
        float s1  = __fadd_rn(__fadd_rn(__fmul_rn(dx1, dx1), __fmul_rn(dy1, dy1)),
                              __fmul_rn(dz1, dz1));
        bool m0 = (__fmul_rn(p0.w, v.w) == 0.0f);
        bool m1 = (__fmul_rn(p1.w, v.w) == 0.0f);
        if (!m0) smax0 = fmaxf(smax0, s0);
        if (!m1) smax1 = fmaxf(smax1, s1);
        k0[u] = ((unsigned long long)(m0 ? INF_BITS : __float_as_uint(s0)) << 32)
                | (unsigned)j;
        k1[u] = ((unsigned long long)(m1 ? INF_BITS : __float_as_uint(s1)) << 32)
                | (unsigned)j;
    }
#pragma unroll
    for (int off = 16; off > 0; off >>= 1) {
        smax0 = fmaxf(smax0, __shfl_xor_sync(0xffffffffu, smax0, off));
        smax1 = fmaxf(smax1, __shfl_xor_sync(0xffffffffu, smax1, off));
    }
    if (lane == 0) wmaxs[wid] = smax0;
    __syncthreads();
    if (tid == 0) {
        float m = wmaxs[0];
        for (int w = 1; w < 8; w++) m = fmaxf(m, wmaxs[w]);
        s_dmx[0] = (m >= 0.0f) ? __fsqrt_rn(__fadd_rn(m, 1e-6f)) : 0.0f;
    }
    __syncthreads();
    if (lane == 0) wmaxs[wid] = smax1;
    __syncthreads();
    if (tid == 0) {
        float m = wmaxs[0];
        for (int w = 1; w < 8; w++) m = fmaxf(m, wmaxs[w]);
        s_dmx[1] = (m >= 0.0f) ? __fsqrt_rn(__fadd_rn(m, 1e-6f)) : 0.0f;
    }
    __syncthreads();   // coords dead; smem re-aliased as cand buffers

#pragma unroll
    for (int r = 0; r < 2; r++) {
        // ---- level 1: histogram on key bits [63:56], threshold 64 ----
        hist[tid] = 0;
        if (tid == 0) { s_nwin = 0; s_nc1 = 0; s_nc2 = 0; }
        __syncthreads();
#pragma unroll
        for (int u = 0; u < 8; u++) {
            unsigned long long kv = r ? k1[u] : k0[u];
            atomicAdd(&hist[(unsigned)(kv >> 56)], 1u);
        }
        __syncthreads();
        scan_pivot(hist, 64u, &s_pivot, &s_base, tid);
        __syncthreads();
        unsigned pv1 = s_pivot, base1 = s_base;
#pragma unroll
        for (int u = 0; u < 8; u++) {
            unsigned long long kv = r ? k1[u] : k0[u];
            unsigned bn = (unsigned)(kv >> 56);
            if (bn < pv1)       win[atomicAdd(&s_nwin, 1u)]   = kv;
            else if (bn == pv1) cand1[atomicAdd(&s_nc1, 1u)]  = kv;
        }
        __syncthreads();

        // ---- level 2: histogram on key bits [55:48] within pivot bin ----
        unsigned need = 64u - base1;
        hist[tid] = 0;
        __syncthreads();
        unsigned nc1 = s_nc1;
        for (unsigned t = tid; t < nc1; t += 256)
            atomicAdd(&hist[(unsigned)(cand1[t] >> 48) & 255u], 1u);
        __syncthreads();
        scan_pivot(hist, need, &s_pivot, &s_base, tid);
        __syncthreads();
        unsigned pv2 = s_pivot;
        for (unsigned t = tid; t < nc1; t += 256) {
            unsigned long long v = cand1[t];
            unsigned bn = (unsigned)(v >> 48) & 255u;
            if (bn < pv2)       win[atomicAdd(&s_nwin, 1u)]  = v;
            else if (bn == pv2) cand2[atomicAdd(&s_nc2, 1u)] = v;
        }
        __syncthreads();

        // ---- exact extraction of remaining finalists (to 64) from cand2 ----
        if (wid == 0) {
            int m2 = (int)s_nc2;
            int nw = (int)s_nwin;
            int rem = 64 - nw;        // >= 1 by construction
            for (int rr = 0; rr < rem; rr++) {
                unsigned long long best = ~0ull; int bp = -1;
                for (int t = lane; t < m2; t += 32) {
                    unsigned long long v = cand2[t];
                    if (v < best) { best = v; bp = t; }
                }
#pragma unroll
                for (int off = 16; off > 0; off >>= 1) {
                    unsigned long long o = __shfl_xor_sync(0xffffffffu, best, off);
                    int op = __shfl_xor_sync(0xffffffffu, bp, off);
                    if (o < best) { best = o; bp = op; }
                }
                if (lane == 0) { win[nw + rr] = best; cand2[bp] = ~0ull; }
                __syncwarp();
            }
        }
        __syncthreads();

        // ---- finalize: exact adj keys for the 64 finalists ----
        if (tid < 64) {
            unsigned long long v = win[tid];
            unsigned sbits = (unsigned)(v >> 32);
            float adj;
            if (sbits == INF_BITS) {
                adj = s_dmx[r];   // masked: adj = dmax exactly
            } else {
                float s  = __uint_as_float(sbits);
                adj = __fsqrt_rn(__fadd_rn(s, 1e-6f));
            }
            win[tid] = ((unsigned long long)__float_as_uint(adj) << 32) |
                       (v & 0xffffffffull);
        }
        __syncthreads();

        // ---- exact bitonic sort of 64 final keys, warp 0; emit first 48 ----
        if (wid == 0) {
            unsigned long long a0 = win[2 * lane], a1 = win[2 * lane + 1];
#pragma unroll
            for (int kk = 2; kk <= 64; kk <<= 1) {
#pragma unroll
                for (int j = kk >> 1; j >= 1; j >>= 1) {
                    bool up = ((2 * lane) & kk) == 0;
                    if (j == 1) {
                        if (up ? (a0 > a1) : (a0 < a1)) {
                            unsigned long long t = a0; a0 = a1; a1 = t;
                        }
                    } else {
                        int d = j >> 1;
                        bool lower = (lane & d) == 0;
                        unsigned long long q0 = __shfl_xor_sync(0xffffffffu, a0, d);
                        unsigned long long q1 = __shfl_xor_sync(0xffffffffu, a1, d);
                        bool keepmin = (up == lower);
                        a0 = keepmin ? (a0 < q0 ? a0 : q0) : (a0 > q0 ? a0 : q0);
                        a1 = keepmin ? (a1 < q1 ? a1 : q1) : (a1 > q1 ? a1 : q1);
                    }
                }
            }
            size_t baseo = (size_t)(b * LL + i0 + r) * KNN;
            int r0 = 2 * lane, r1 = 2 * lane + 1;
            if (r0 < KNN) {
                int j = (int)(unsigned)(a0 & 0xffffffffull);
                g_eidx[baseo + r0] = j;
                if (outI) outI[baseo + r0] = (float)j;
            }
            if (r1 < KNN) {
                int j = (int)(unsigned)(a1 & 0xffffffffull);
                g_eidx[baseo + r1] = j;
                if (outI) outI[baseo + r1] = (float)j;
            }
        }
        __syncthreads();   // win/hist/counters reused for row r=1
    }
}

// ---------------------------------------------------------------------------
// Kernel 3 (hot, unchanged from R12/R13 best): 2 nodes per CTA (96x128).
// fp16 m16n8k16 MMA (fp32 accum), A via ldmatrix.x4, B scalar LDS,
// direct-store LN epilogue, 3 CTAs/SM.
// ---------------------------------------------------------------------------
__global__ void __launch_bounds__(256, 3) edge_kernel(
    const int* __restrict__ ridx, const int* __restrict__ chain,
    const float* __restrict__ Wpos, const float* __restrict__ bpos,
    const float* __restrict__ gamma_, const float* __restrict__ beta_,
    float* __restrict__ outE) {
    extern __shared__ unsigned dsm[];
    __shared__ float ssat[2 * 15];
    __shared__ float snat[96 * 15];
    __shared__ float gam[ED], bet[ED];
    __shared__ float bposs[16];
    __shared__ int   eidx_s[96];
    __shared__ int   dcls[96];
    __shared__ float2 psum[96][4];     // per-(row, colgroup) partial (sum, sumsq)

    int tid  = threadIdx.x;
    int wid  = tid >> 5;
    int lane = tid & 31;
    int gid  = lane >> 2, tg = lane & 3;
    int node0 = 2 * blockIdx.x;
    int b = node0 >> 11;

    unsigned smA = smem_u32(dsm);
    unsigned smW = smA + 2 * AWRD * 4;

    if (tid < ED) { gam[tid] = gamma_[tid]; bet[tid] = beta_[tid]; }
    if (tid < 16) bposs[tid] = bpos[tid];
    if (tid < 96) eidx_s[tid] = g_eidx[(size_t)node0 * KNN + tid];
    if (tid >= 128 && tid < 158) ssat[tid - 128] = g_atoms[(size_t)node0 * 15 + (tid - 128)];
    __syncthreads();

    if (tid < 96) {
        int nl = tid / KNN;
        int j  = eidx_s[tid];
        int ng = node0 + nl;
        int off  = ridx[ng] - ridx[b * LL + j];
        int same = (chain[ng] == chain[b * LL + j]);
        int d = off + 32;
        d = d < 0 ? 0 : (d > 64 ? 64 : d);
        dcls[tid] = same ? d : 65;
    }
    for (int t = tid; t < 96 * 15; t += 256) {
        int n = t / 15, c = t % 15;
        snat[t] = g_atoms[(size_t)(b * LL + eidx_s[n]) * 15 + c];
    }

    // prologue: W chunks 0,1 into ring stages 0,1 (8KB each, 2 cp16/thread)
#pragma unroll
    for (int q = 0; q < 2; q++) {
        unsigned bst = smW + (unsigned)(q & 3) * WWRD * 4;
#pragma unroll
        for (int e = 0; e < 2; e++) {
            int idx = tid + e * 256;            // 0..511
            int r = idx >> 5, g = idx & 31;     // k-pair row 0..15, granule 0..31
            cp16(bst + (unsigned)(r * WSTR + g * 4) * 4,
                 g_Wh + (size_t)(q * 16 + r) * ED + g * 4);
        }
        cp_commit();
    }
    __syncthreads();   // snat/ssat/dcls visible before feature compute

    // prologue: features chunk 0 (positional + pair 0) into A stage 0
    {
        uint4* Ab = (uint4*)dsm;
        if (tid < 96) {
            int row = tid, dc = dcls[row];
            unsigned w[8];
#pragma unroll
            for (int q = 0; q < 8; q++)
                w[q] = packh2(Wpos[dc * 16 + 2 * q]     + bposs[2 * q],
                              Wpos[dc * 16 + 2 * q + 1] + bposs[2 * q + 1]);
            Ab[(row * ASTR) >> 2]       = make_uint4(w[0], w[1], w[2], w[3]);
            Ab[(row * ASTR + 4) >> 2]   = make_uint4(w[4], w[5], w[6], w[7]);
        } else if (tid < 192) {
            int row = tid - 96;                 // pair 0 (Ca-Ca)
            int nl = row / KNN;
            float dx = ssat[nl * 15 + 0] - snat[row * 15 + 0];
            float dy = ssat[nl * 15 + 1] - snat[row * 15 + 1];
            float dz = ssat[nl * 15 + 2] - snat[row * 15 + 2];
            float Dp = sqrtf(dx * dx + dy * dy + dz * dz + 1e-6f);
            unsigned w[8];
#pragma unroll
            for (int q = 0; q < 8; q++) {
                float mu0 = 2.0f + (20.0f / 15.0f) * (float)(2 * q);
                float mu1 = 2.0f + (20.0f / 15.0f) * (float)(2 * q + 1);
                float z0 = (Dp - mu0) * 0.8f, z1 = (Dp - mu1) * 0.8f;
                w[q] = packh2(__expf(-z0 * z0), __expf(-z1 * z1));
            }
            Ab[(row * ASTR + 8) >> 2]   = make_uint4(w[0], w[1], w[2], w[3]);
            Ab[(row * ASTR + 12) >> 2]  = make_uint4(w[4], w[5], w[6], w[7]);
        }
    }

    float acc[3][4][4];
#pragma unroll
    for (int rt = 0; rt < 3; rt++)
#pragma unroll
        for (int j = 0; j < 4; j++)
#pragma unroll
            for (int c = 0; c < 4; c++) acc[rt][j][c] = 0.0f;

    int rg = wid >> 2, cg = wid & 3;
    int rowbase = rg * 48;
    int colbase = cg * 32;
    // ldmatrix lane address component: row = rowbase + (lane&15), koff = (lane>>4)*4
    unsigned lmBase = (unsigned)(((rowbase + (lane & 15)) * ASTR + ((lane >> 4) << 2)) * 4);

    for (int c = 0; c < NCH; c++) {
        // ---- issue W chunk c+2 into ring stage (c+2)&3 ----
        if (c + 2 < NCH) {
            int q = c + 2;
            unsigned bst = smW + (unsigned)(q & 3) * WWRD * 4;
#pragma unroll
            for (int e = 0; e < 2; e++) {
                int idx = tid + e * 256;
                int r = idx >> 5, g = idx & 31;
                cp16(bst + (unsigned)(r * WSTR + g * 4) * 4,
                     g_Wh + (size_t)(q * 16 + r) * ED + g * 4);
            }
        }
        cp_commit();
        cp_wait2();              // W chunk c landed
        __syncthreads();         // A(c) features + W(c) visible; orders
                                 // MMA(c-1) reads before features(c+1) writes

        // ---- MMA on chunk c: 2 k16 steps (reads A[c&1], W[c&3]) ----
        unsigned aBase = smA + (unsigned)((c & 1) * AWRD * 4) + lmBase;
        unsigned* Wb = dsm + 2 * AWRD + (c & 3) * WWRD;
#pragma unroll
        for (int s = 0; s < 2; s++) {
            int kb = s * 8;      // u32 (half2) column base
            unsigned a[3][4];
#pragma unroll
            for (int rt = 0; rt < 3; rt++)
                ldmA(a[rt], aBase + (unsigned)((rt * 16 * ASTR + kb) * 4));
            unsigned bf[4][2];
#pragma unroll
            for (int j = 0; j < 4; j++) {
                bf[j][0] = Wb[(kb + tg) * WSTR + colbase + j * 8 + gid];
                bf[j][1] = Wb[(kb + tg + 4) * WSTR + colbase + j * 8 + gid];
            }
#pragma unroll
            for (int rt = 0; rt < 3; rt++)
#pragma unroll
                for (int j = 0; j < 4; j++)
                    MMA_F16(acc[rt][j], a[rt], bf[j]);
        }

        // ---- overlap: compute features chunk c+1 into A[(c+1)&1] ----
        if (c + 1 < NCH && tid < 192) {
            uint4* An = (uint4*)(dsm + ((c + 1) & 1) * AWRD);
            int pi = tid / 96, row = tid % 96;
            int nl = row / KNN;
            int p  = 2 * (c + 1) - 1 + pi;         // pair 1..24
            int a1 = p / 5, a2 = p % 5;
            float dx = ssat[nl * 15 + a1 * 3 + 0] - snat[row * 15 + a2 * 3 + 0];
            float dy = ssat[nl * 15 + a1 * 3 + 1] - snat[row * 15 + a2 * 3 + 1];
            float dz = ssat[nl * 15 + a1 * 3 + 2] - snat[row * 15 + a2 * 3 + 2];
            float Dp = sqrtf(dx * dx + dy * dy + dz * dz + 1e-6f);
            int cb = 8 * pi;
            unsigned w[8];
#pragma unroll
            for (int q = 0; q < 8; q++) {
                float mu0 = 2.0f + (20.0f / 15.0f) * (float)(2 * q);
                float mu1 = 2.0f + (20.0f / 15.0f) * (float)(2 * q + 1);
                float z0 = (Dp - mu0) * 0.8f, z1 = (Dp - mu1) * 0.8f;
                w[q] = packh2(__expf(-z0 * z0), __expf(-z1 * z1));
            }
            An[(row * ASTR + cb) >> 2]     = make_uint4(w[0], w[1], w[2], w[3]);
            An[(row * ASTR + cb + 4) >> 2] = make_uint4(w[4], w[5], w[6], w[7]);
        }
    }

    // ---- epilogue: per-row partials across the 4 colgroup warps ----
#pragma unroll
    for (int rt = 0; rt < 3; rt++) {
        float s0 = 0.f, q0 = 0.f, s1 = 0.f, q1 = 0.f;
#pragma unroll
        for (int j = 0; j < 4; j++) {
            s0 += acc[rt][j][0] + acc[rt][j][1];
            q0 += acc[rt][j][0] * acc[rt][j][0] + acc[rt][j][1] * acc[rt][j][1];
            s1 += acc[rt][j][2] + acc[rt][j][3];
            q1 += acc[rt][j][2] * acc[rt][j][2] + acc[rt][j][3] * acc[rt][j][3];
        }
#pragma unroll
        for (int m = 1; m <= 2; m <<= 1) {
            s0 += __shfl_xor_sync(0xffffffffu, s0, m);
            q0 += __shfl_xor_sync(0xffffffffu, q0, m);
            s1 += __shfl_xor_sync(0xffffffffu, s1, m);
            q1 += __shfl_xor_sync(0xffffffffu, q1, m);
        }
        if (tg == 0) {
            int r0 = rowbase + rt * 16 + gid;
            psum[r0][cg]     = make_float2(s0, q0);
            psum[r0 + 8][cg] = make_float2(s1, q1);
        }
    }
    __syncthreads();

    // ---- LN in registers + direct float2 stores to gmem ----
    size_t obase = (size_t)node0 * KNN * ED;
#pragma unroll
    for (int rt = 0; rt < 3; rt++) {
        int r0 = rowbase + rt * 16 + gid;
        float2 pa0 = psum[r0][0], pa1 = psum[r0][1];
        float2 pa2 = psum[r0][2], pa3 = psum[r0][3];
        float2 pb0 = psum[r0 + 8][0], pb1 = psum[r0 + 8][1];
        float2 pb2 = psum[r0 + 8][2], pb3 = psum[r0 + 8][3];
        float mean0 = (pa0.x + pa1.x + pa2.x + pa3.x) * (1.0f / 128.0f);
        float var0  = (pa0.y + pa1.y + pa2.y + pa3.y) * (1.0f / 128.0f) - mean0 * mean0;
        float rs0   = rsqrtf(var0 + 1e-5f);
        float mean1 = (pb0.x + pb1.x + pb2.x + pb3.x) * (1.0f / 128.0f);
        float var1  = (pb0.y + pb1.y + pb2.y + pb3.y) * (1.0f / 128.0f) - mean1 * mean1;
        float rs1   = rsqrtf(var1 + 1e-5f);
        float* dst0 = outE + obase + (size_t)r0 * ED;
        float* dst1 = dst0 + 8 * ED;
#pragma unroll
        for (int j = 0; j < 4; j++) {
            int col = colbase + j * 8 + 2 * tg;
            float g0 = gam[col], g1 = gam[col + 1];
            float b0 = bet[col], b1 = bet[col + 1];
            *(float2*)(dst0 + col) =
                make_float2((acc[rt][j][0] - mean0) * rs0 * g0 + b0,
                            (acc[rt][j][1] - mean0) * rs0 * g1 + b1);
            *(float2*)(dst1 + col) =
                make_float2((acc[rt][j][2] - mean1) * rs1 * g0 + b0,
                            (acc[rt][j][3] - mean1) * rs1 * g1 + b1);
        }
    }
}

// ---------------------------------------------------------------------------
extern "C" void kernel_launch(void* const* d_in, const int* in_sizes, int n_in,
                              void* d_out, int out_size) {
    const float* X     = (const float*)d_in[0];
    const float* mask  = (const float*)d_in[1];
    const int*   ridx  = (const int*)d_in[2];
    const int*   chain = (const int*)d_in[3];
    const float* Wpos  = (const float*)d_in[4];
    const float* bpos  = (const float*)d_in[5];
    const float* Wedge = (const float*)d_in[6];
    const float* gam   = (const float*)d_in[7];
    const float* bet   = (const float*)d_in[8];

    float* outE = (float*)d_out;
    size_t nE = (size_t)BB * LL * KNN * ED;
    float* outI = ((size_t)out_size > nE) ? (outE + nE) : nullptr;

    prep_kernel<<<16 + (208 * ED + 255) / 256, 256>>>(X, mask, Wedge);
    topk_kernel<<<BB * LL / 2, 256>>>(outI);

    static const int smemK3 = DSMW * 4;   // 49152 B (pipeline only)
    cudaFuncSetAttribute(edge_kernel,
                         cudaFuncAttributeMaxDynamicSharedMemorySize, smemK3);
    edge_kernel<<<BB * LL / 2, 256, smemK3>>>(ridx, chain, Wpos, bpos,
                                              gam, bet, outE);
    (void)in_sizes; (void)n_in;
}

// round 15
// speedup vs baseline: 1.0122x; 1.0122x over previous
#include <cuda_runtime.h>
#include <cuda_fp16.h>
#include <cstdint>

#define BB   2
#define LL   2048
#define KNN  48
#define ED   128
#define NCH  13            // 13 K-chunks of 32 fp32 cols = K=416

#define ASTR 20            // A smem row stride in u32 (16 half2 + 4 pad)
#define WSTR 132           // W smem row stride in u32 (128 + 4 pad)
#define AWRD (96 * ASTR)   // words per A stage = 1920
#define WWRD (16 * WSTR)   // words per W stage = 2112 (16 k-pair rows)
#define DSMW (2 * AWRD + 4 * WWRD)   // 12288 words = 49152 B

// exp cutoff: e^{-t} < 2^-25 for t > 25*ln2 -> value rounds to fp16 zero
#define EXP_CUT 17.33f

// scratch (allocation-free rule: __device__ globals)
__device__ float    g_atoms[BB * LL * 15];
__device__ float4   g_ca[BB * LL];    // packed (Ca.xyz, mask) for topk
__device__ int      g_eidx[BB * LL * KNN];
__device__ unsigned g_Wh[208 * ED];   // W as half2 k-pairs: [k/2][n]

__device__ __forceinline__ unsigned smem_u32(const void* p) {
    unsigned a;
    asm("{ .reg .u64 t; cvta.to.shared.u64 t, %1; cvt.u32.u64 %0, t; }"
        : "=r"(a) : "l"(p));
    return a;
}
__device__ __forceinline__ void cp16(unsigned dst, const void* src) {
    asm volatile("cp.async.cg.shared.global [%0], [%1], 16;" :: "r"(dst), "l"(src));
}
__device__ __forceinline__ void cp_commit() {
    asm volatile("cp.async.commit_group;" ::: "memory");
}
__device__ __forceinline__ void cp_wait2() {
    asm volatile("cp.async.wait_group 2;" ::: "memory");
}
__device__ __forceinline__ unsigned packh2(float a, float b) {
    __half2 h = __floats2half2_rn(a, b);
    return *(unsigned*)&h;
}
__device__ __forceinline__ float rbf_exp(float z) {
    float t = z * z;
    return (t > EXP_CUT) ? 0.0f : __expf(-t);
}
__device__ __forceinline__ void ldmA(unsigned* a, unsigned addr) {
    asm volatile(
        "ldmatrix.sync.aligned.m8n8.x4.shared.b16 {%0,%1,%2,%3}, [%4];"
        : "=r"(a[0]), "=r"(a[1]), "=r"(a[2]), "=r"(a[3]) : "r"(addr));
}

#define MMA_F16(d, a, b)                                                      \
    asm volatile(                                                             \
        "mma.sync.aligned.m16n8k16.row.col.f32.f16.f16.f32 "                  \
        "{%0,%1,%2,%3}, {%4,%5,%6,%7}, {%8,%9}, {%0,%1,%2,%3};"               \
        : "+f"(d[0]), "+f"(d[1]), "+f"(d[2]), "+f"(d[3])                      \
        : "r"(a[0]), "r"(a[1]), "r"(a[2]), "r"(a[3]), "r"(b[0]), "r"(b[1]))

// ---------------------------------------------------------------------------
// Kernel 0 (merged prep): blocks 0..15 build atoms + packed (Ca,mask);
// blocks 16+ pack W into half2 k-pairs g_Wh[kk][n] (k-major rows).
// ---------------------------------------------------------------------------
__global__ void prep_kernel(const float* __restrict__ X,
                            const float* __restrict__ mask,
                            const float* __restrict__ W) {
    if (blockIdx.x < 16) {
        int idx = blockIdx.x * 256 + threadIdx.x;
        if (idx >= BB * LL) return;
        const float* x = X + (size_t)idx * 12;
        float Nx = x[0],  Ny = x[1],  Nz = x[2];
        float Cax = x[3], Cay = x[4], Caz = x[5];
        float Cx = x[6],  Cy = x[7],  Cz = x[8];
        float Ox = x[9],  Oy = x[10], Oz = x[11];

        float bx = Cax - Nx,  by = Cay - Ny,  bz = Caz - Nz;
        float cx = Cx - Cax,  cy = Cy - Cay,  cz = Cz - Caz;
        float ax = by * cz - bz * cy;
        float ay = bz * cx - bx * cz;
        float az = bx * cy - by * cx;
        float Cbx = -0.58273431f * ax + 0.56802827f * bx - 0.54067466f * cx + Cax;
        float Cby = -0.58273431f * ay + 0.56802827f * by - 0.54067466f * cy + Cay;
        float Cbz = -0.58273431f * az + 0.56802827f * bz - 0.54067466f * cz + Caz;

        float* o = g_atoms + (size_t)idx * 15;
        o[0]  = Cax; o[1]  = Cay; o[2]  = Caz;
        o[3]  = Nx;  o[4]  = Ny;  o[5]  = Nz;
        o[6]  = Cx;  o[7]  = Cy;  o[8]  = Cz;
        o[9]  = Ox;  o[10] = Oy;  o[11] = Oz;
        o[12] = Cbx; o[13] = Cby; o[14] = Cbz;
        g_ca[idx] = make_float4(Cax, Cay, Caz, mask[idx]);
    } else {
        int idx = (blockIdx.x - 16) * 256 + threadIdx.x;
        if (idx >= 208 * ED) return;
        int kk = idx / ED, n = idx % ED;
        g_Wh[idx] = packh2(W[(2 * kk) * ED + n], W[(2 * kk + 1) * ED + n]);
    }
}

// ---------------------------------------------------------------------------
// Radix-select helper (warp 0 scans hist[256] for pivot crossing thr)
// ---------------------------------------------------------------------------
__device__ __forceinline__ void scan_pivot(const unsigned* hist, unsigned thr,
                                           unsigned* s_pivot, unsigned* s_base,
                                           int tid) {
    if (tid < 32) {
        unsigned v[8], pre[8], s = 0;
#pragma unroll
        for (int j = 0; j < 8; j++) { v[j] = hist[tid * 8 + j]; pre[j] = s; s += v[j]; }
        unsigned tot = s, x = tot;
#pragma unroll
        for (int off = 1; off < 32; off <<= 1) {
            unsigned y = __shfl_up_sync(0xffffffffu, x, off);
            if (tid >= off) x += y;
        }
        unsigned ex = x - tot;
        if (ex < thr && ex + tot >= thr) {
#pragma unroll
            for (int j = 0; j < 8; j++) {
                unsigned cb = ex + pre[j];
                if (cb < thr && cb + v[j] >= thr) { *s_pivot = tid * 8 + j; *s_base = cb; }
            }
        }
    }
}

// ---------------------------------------------------------------------------
// Kernel 2 (R13 best version): top-K. Selection on squared distances
// (FMA only); smallest-64 radix superset -> exact sqrt on 64 finalists ->
// exact bitonic sort (bit-identical E_idx). One row per block.
// ---------------------------------------------------------------------------
__global__ void __launch_bounds__(256) topk_kernel(float* __restrict__ outI) {
    __shared__ __align__(16) char sbuf[32768];
    float* cxs = (float*)sbuf;
    float* cys = cxs + LL;
    float* czs = cys + LL;
    float* mms = czs + LL;
    unsigned long long* cand1 = (unsigned long long*)sbuf;            // 16KB
    unsigned long long* cand2 = (unsigned long long*)(sbuf + 16384);  // 16KB
    __shared__ unsigned hist[256];
    __shared__ unsigned long long win[64];
    __shared__ unsigned s_nwin, s_nc1, s_nc2, s_pivot, s_base;
    __shared__ float wmaxs[8];
    __shared__ float s_dmx;

    const unsigned INF_BITS = 0x7F800000u;

    int b   = blockIdx.x >> 11;
    int i   = blockIdx.x & (LL - 1);
    int tid = threadIdx.x;
    int lane = tid & 31, wid = tid >> 5;

    for (int t = tid; t < LL; t += 256) {
        float4 v = g_ca[b * LL + t];
        cxs[t] = v.x; cys[t] = v.y; czs[t] = v.z; mms[t] = v.w;
    }
    __syncthreads();

    float xi = cxs[i], yi = cys[i], zi = czs[i], mi = mms[i];
    unsigned long long k[8];
    float smax = -1.0f;           // max squared dist over unmasked entries
#pragma unroll
    for (int u = 0; u < 8; u++) {
        int j = tid * 8 + u;
        // exact fp32 op order, no fma-contraction (matches XLA up to sqrt)
        float dx = __fsub_rn(cxs[j], xi);
        float dy = __fsub_rn(cys[j], yi);
        float dz = __fsub_rn(czs[j], zi);
        float s  = __fadd_rn(__fadd_rn(__fmul_rn(dx, dx), __fmul_rn(dy, dy)),
                             __fmul_rn(dz, dz));
        float mij = __fmul_rn(mi, mms[j]);
        bool masked = (mij == 0.0f);
        if (!masked) smax = fmaxf(smax, s);
        unsigned sbits = masked ? INF_BITS : __float_as_uint(s);
        k[u] = ((unsigned long long)sbits << 32) | (unsigned)j;
    }
#pragma unroll
    for (int off = 16; off > 0; off >>= 1)
        smax = fmaxf(smax, __shfl_xor_sync(0xffffffffu, smax, off));
    if (lane == 0) wmaxs[wid] = smax;
    __syncthreads();
    if (tid == 0) {
        float m = wmaxs[0];
        for (int w = 1; w < 8; w++) m = fmaxf(m, wmaxs[w]);
        s_dmx = (m >= 0.0f) ? __fsqrt_rn(__fadd_rn(m, 1e-6f)) : 0.0f;
    }
    __syncthreads();   // done reading coordinate smem; safe to alias as cand*

    // ---- level 1: histogram on key bits [63:56], threshold 64 ----
    hist[tid] = 0;
    if (tid == 0) { s_nwin = 0; s_nc1 = 0; s_nc2 = 0; }
    __syncthreads();
#pragma unroll
    for (int u = 0; u < 8; u++)
        atomicAdd(&hist[(unsigned)(k[u] >> 56)], 1u);
    __syncthreads();
    scan_pivot(hist, 64u, &s_pivot, &s_base, tid);
    __syncthreads();
    unsigned p1 = s_pivot, base1 = s_base;
#pragma unroll
    for (int u = 0; u < 8; u++) {
        unsigned bn = (unsigned)(k[u] >> 56);
        if (bn < p1)       win[atomicAdd(&s_nwin, 1u)]   = k[u];
        else if (bn == p1) cand1[atomicAdd(&s_nc1, 1u)]  = k[u];
    }
    __syncthreads();

    // ---- level 2: histogram on key bits [55:48] within pivot bin ----
    unsigned need = 64u - base1;
    hist[tid] = 0;
    __syncthreads();
    unsigned nc1 = s_nc1;
    for (unsigned t = tid; t < nc1; t += 256)
        atomicAdd(&hist[(unsigned)(cand1[t] >> 48) & 255u], 1u);
    __syncthreads();
    scan_pivot(hist, need, &s_pivot, &s_base, tid);
    __syncthreads();
    unsigned p2 = s_pivot;
    for (unsigned t = tid; t < nc1; t += 256) {
        unsigned long long v = cand1[t];
        unsigned bn = (unsigned)(v >> 48) & 255u;
        if (bn < p2)       win[atomicAdd(&s_nwin, 1u)]  = v;
        else if (bn == p2) cand2[atomicAdd(&s_nc2, 1u)] = v;
    }
    __syncthreads();

    // ---- exact extraction of remaining finalists (to 64) from cand2 ----
    if (wid == 0) {
        int m2 = (int)s_nc2;
        int nw = (int)s_nwin;
        int rem = 64 - nw;        // >= 1 by construction
        for (int r = 0; r < rem; r++) {
            unsigned long long best = ~0ull; int bp = -1;
            for (int t = lane; t < m2; t += 32) {
                unsigned long long v = cand2[t];
                if (v < best) { best = v; bp = t; }
            }
#pragma unroll
            for (int off = 16; off > 0; off >>= 1) {
                unsigned long long o = __shfl_xor_sync(0xffffffffu, best, off);
                int op = __shfl_xor_sync(0xffffffffu, bp, off);
                if (o < best) { best = o; bp = op; }
            }
            if (lane == 0) { win[nw + r] = best; cand2[bp] = ~0ull; }
            __syncwarp();
        }
    }
    __syncthreads();

    // ---- finalize: exact adj keys for the 64 finalists (64 sqrts total) ----
    if (tid < 64) {
        unsigned long long v = win[tid];
        unsigned sbits = (unsigned)(v >> 32);
        float adj;
        if (sbits == INF_BITS) {
            adj = s_dmx;   // masked: dv=0, (1-m2)=1 -> adj = dmax exactly
        } else {
            float s  = __uint_as_float(sbits);
            adj = __fsqrt_rn(__fadd_rn(s, 1e-6f));
        }
        win[tid] = ((unsigned long long)__float_as_uint(adj) << 32) |
                   (v & 0xffffffffull);
    }
    __syncthreads();

    // ---- exact bitonic sort of the 64 final keys, warp 0; emit first 48 ----
    if (wid == 0) {
        unsigned long long a0 = win[2 * lane], a1 = win[2 * lane + 1];
#pragma unroll
        for (int kk = 2; kk <= 64; kk <<= 1) {
#pragma unroll
            for (int j = kk >> 1; j >= 1; j >>= 1) {
                bool up = ((2 * lane) & kk) == 0;
                if (j == 1) {
                    if (up ? (a0 > a1) : (a0 < a1)) {
                        unsigned long long t = a0; a0 = a1; a1 = t;
                    }
                } else {
                    int d = j >> 1;
                    bool lower = (lane & d) == 0;
                    unsigned long long q0 = __shfl_xor_sync(0xffffffffu, a0, d);
                    unsigned long long q1 = __shfl_xor_sync(0xffffffffu, a1, d);
                    bool keepmin = (up == lower);
                    a0 = keepmin ? (a0 < q0 ? a0 : q0) : (a0 > q0 ? a0 : q0);
                    a1 = keepmin ? (a1 < q1 ? a1 : q1) : (a1 > q1 ? a1 : q1);
                }
            }
        }
        size_t baseo = (size_t)(b * LL + i) * KNN;
        int r0 = 2 * lane, r1 = 2 * lane + 1;
        if (r0 < KNN) {
            int j = (int)(unsigned)(a0 & 0xffffffffull);
            g_eidx[baseo + r0] = j;
            if (outI) outI[baseo + r0] = (float)j;
        }
        if (r1 < KNN) {
            int j = (int)(unsigned)(a1 & 0xffffffffull);
            g_eidx[baseo + r1] = j;
            if (outI) outI[baseo + r1] = (float)j;
        }
    }
}

// ---------------------------------------------------------------------------
// Kernel 3 (hot): 2 nodes per CTA (96x128). fp16 m16n8k16 MMA (fp32 accum).
// A via ldmatrix.x4, B scalar LDS, direct-store LN epilogue, 3 CTAs/SM.
// NEW: RBF exps skipped when e^{-z^2} rounds to fp16 zero (z^2 > 25 ln2) —
// bit-identical fp16 features, ~40% fewer MUFU ops in the feature phase.
// ---------------------------------------------------------------------------
__global__ void __launch_bounds__(256, 3) edge_kernel(
    const int* __restrict__ ridx, const int* __restrict__ chain,
    const float* __restrict__ Wpos, const float* __restrict__ bpos,
    const float* __restrict__ gamma_, const float* __restrict__ beta_,
    float* __restrict__ outE) {
    extern __shared__ unsigned dsm[];
    __shared__ float ssat[2 * 15];
    __shared__ float snat[96 * 15];
    __shared__ float gam[ED], bet[ED];
    __shared__ float bposs[16];
    __shared__ int   eidx_s[96];
    __shared__ int   dcls[96];
    __shared__ float2 psum[96][4];     // per-(row, colgroup) partial (sum, sumsq)

    int tid  = threadIdx.x;
    int wid  = tid >> 5;
    int lane = tid & 31;
    int gid  = lane >> 2, tg = lane & 3;
    int node0 = 2 * blockIdx.x;
    int b = node0 >> 11;

    unsigned smA = smem_u32(dsm);
    unsigned smW = smA + 2 * AWRD * 4;

    if (tid < ED) { gam[tid] = gamma_[tid]; bet[tid] = beta_[tid]; }
    if (tid < 16) bposs[tid] = bpos[tid];
    if (tid < 96) eidx_s[tid] = g_eidx[(size_t)node0 * KNN + tid];
    if (tid >= 128 && tid < 158) ssat[tid - 128] = g_atoms[(size_t)node0 * 15 + (tid - 128)];
    __syncthreads();

    if (tid < 96) {
        int nl = tid / KNN;
        int j  = eidx_s[tid];
        int ng = node0 + nl;
        int off  = ridx[ng] - ridx[b * LL + j];
        int same = (chain[ng] == chain[b * LL + j]);
        int d = off + 32;
        d = d < 0 ? 0 : (d > 64 ? 64 : d);
        dcls[tid] = same ? d : 65;
    }
    for (int t = tid; t < 96 * 15; t += 256) {
        int n = t / 15, c = t % 15;
        snat[t] = g_atoms[(size_t)(b * LL + eidx_s[n]) * 15 + c];
    }

    // prologue: W chunks 0,1 into ring stages 0,1 (8KB each, 2 cp16/thread)
#pragma unroll
    for (int q = 0; q < 2; q++) {
        unsigned bst = smW + (unsigned)(q & 3) * WWRD * 4;
#pragma unroll
        for (int e = 0; e < 2; e++) {
            int idx = tid + e * 256;            // 0..511
            int r = idx >> 5, g = idx & 31;     // k-pair row 0..15, granule 0..31
            cp16(bst + (unsigned)(r * WSTR + g * 4) * 4,
                 g_Wh + (size_t)(q * 16 + r) * ED + g * 4);
        }
        cp_commit();
    }
    __syncthreads();   // snat/ssat/dcls visible before feature compute

    // prologue: features chunk 0 (positional + pair 0) into A stage 0
    {
        uint4* Ab = (uint4*)dsm;
        if (tid < 96) {
            int row = tid, dc = dcls[row];
            unsigned w[8];
#pragma unroll
            for (int q = 0; q < 8; q++)
                w[q] = packh2(Wpos[dc * 16 + 2 * q]     + bposs[2 * q],
                              Wpos[dc * 16 + 2 * q + 1] + bposs[2 * q + 1]);
            Ab[(row * ASTR) >> 2]       = make_uint4(w[0], w[1], w[2], w[3]);
            Ab[(row * ASTR + 4) >> 2]   = make_uint4(w[4], w[5], w[6], w[7]);
        } else if (tid < 192) {
            int row = tid - 96;                 // pair 0 (Ca-Ca)
            int nl = row / KNN;
            float dx = ssat[nl * 15 + 0] - snat[row * 15 + 0];
            float dy = ssat[nl * 15 + 1] - snat[row * 15 + 1];
            float dz = ssat[nl * 15 + 2] - snat[row * 15 + 2];
            float Dp = sqrtf(dx * dx + dy * dy + dz * dz + 1e-6f);
            unsigned w[8];
#pragma unroll
            for (int q = 0; q < 8; q++) {
                float mu0 = 2.0f + (20.0f / 15.0f) * (float)(2 * q);
                float mu1 = 2.0f + (20.0f / 15.0f) * (float)(2 * q + 1);
                float z0 = (Dp - mu0) * 0.8f, z1 = (Dp - mu1) * 0.8f;
                w[q] = packh2(rbf_exp(z0), rbf_exp(z1));
            }
            Ab[(row * ASTR + 8) >> 2]   = make_uint4(w[0], w[1], w[2], w[3]);
            Ab[(row * ASTR + 12) >> 2]  = make_uint4(w[4], w[5], w[6], w[7]);
        }
    }

    float acc[3][4][4];
#pragma unroll
    for (int rt = 0; rt < 3; rt++)
#pragma unroll
        for (int j = 0; j < 4; j++)
#pragma unroll
            for (int c = 0; c < 4; c++) acc[rt][j][c] = 0.0f;

    int rg = wid >> 2, cg = wid & 3;
    int rowbase = rg * 48;
    int colbase = cg * 32;
    // ldmatrix lane address component: row = rowbase + (lane&15), koff = (lane>>4)*4
    unsigned lmBase = (unsigned)(((rowbase + (lane & 15)) * ASTR + ((lane >> 4) << 2)) * 4);

    for (int c = 0; c < NCH; c++) {
        // ---- issue W chunk c+2 into ring stage (c+2)&3 ----
        if (c + 2 < NCH) {
            int q = c + 2;
            unsigned bst = smW + (unsigned)(q & 3) * WWRD * 4;
#pragma unroll
            for (int e = 0; e < 2; e++) {
                int idx = tid + e * 256;
                int r = idx >> 5, g = idx & 31;
                cp16(bst + (unsigned)(r * WSTR + g * 4) * 4,
                     g_Wh + (size_t)(q * 16 + r) * ED + g * 4);
            }
        }
        cp_commit();
        cp_wait2();              // W chunk c landed
        __syncthreads();         // A(c) features + W(c) visible; orders
                                 // MMA(c-1) reads before features(c+1) writes

        // ---- MMA on chunk c: 2 k16 steps (reads A[c&1], W[c&3]) ----
        unsigned aBase = smA + (unsigned)((c & 1) * AWRD * 4) + lmBase;
        unsigned* Wb = dsm + 2 * AWRD + (c & 3) * WWRD;
#pragma unroll
        for (int s = 0; s < 2; s++) {
            int kb = s * 8;      // u32 (half2) column base
            unsigned a[3][4];
#pragma unroll
            for (int rt = 0; rt < 3; rt++)
                ldmA(a[rt], aBase + (unsigned)((rt * 16 * ASTR + kb) * 4));
            unsigned bf[4][2];
#pragma unroll
            for (int j = 0; j < 4; j++) {
                bf[j][0] = Wb[(kb + tg) * WSTR + colbase + j * 8 + gid];
                bf[j][1] = Wb[(kb + tg + 4) * WSTR + colbase + j * 8 + gid];
            }
#pragma unroll
            for (int rt = 0; rt < 3; rt++)
#pragma unroll
                for (int j = 0; j < 4; j++)
                    MMA_F16(acc[rt][j], a[rt], bf[j]);
        }

        // ---- overlap: compute features chunk c+1 into A[(c+1)&1] ----
        if (c + 1 < NCH && tid < 192) {
            uint4* An = (uint4*)(dsm + ((c + 1) & 1) * AWRD);
            int pi = tid / 96, row = tid % 96;
            int nl = row / KNN;
            int p  = 2 * (c + 1) - 1 + pi;         // pair 1..24
            int a1 = p / 5, a2 = p % 5;
            float dx = ssat[nl * 15 + a1 * 3 + 0] - snat[row * 15 + a2 * 3 + 0];
            float dy = ssat[nl * 15 + a1 * 3 + 1] - snat[row * 15 + a2 * 3 + 1];
            float dz = ssat[nl * 15 + a1 * 3 + 2] - snat[row * 15 + a2 * 3 + 2];
            float Dp = sqrtf(dx * dx + dy * dy + dz * dz + 1e-6f);
            int cb = 8 * pi;
            unsigned w[8];
#pragma unroll
            for (int q = 0; q < 8; q++) {
                float mu0 = 2.0f + (20.0f / 15.0f) * (float)(2 * q);
                float mu1 = 2.0f + (20.0f / 15.0f) * (float)(2 * q + 1);
                float z0 = (Dp - mu0) * 0.8f, z1 = (Dp - mu1) * 0.8f;
                w[q] = packh2(rbf_exp(z0), rbf_exp(z1));
            }
            An[(row * ASTR + cb) >> 2]     = make_uint4(w[0], w[1], w[2], w[3]);
            An[(row * ASTR + cb + 4) >> 2] = make_uint4(w[4], w[5], w[6], w[7]);
        }
    }

    // ---- epilogue: per-row partials across the 4 colgroup warps ----
#pragma unroll
    for (int rt = 0; rt < 3; rt++) {
        float s0 = 0.f, q0 = 0.f, s1 = 0.f, q1 = 0.f;
#pragma unroll
        for (int j = 0; j < 4; j++) {
            s0 += acc[rt][j][0] + acc[rt][j][1];
            q0 += acc[rt][j][0] * acc[rt][j][0] + acc[rt][j][1] * acc[rt][j][1];
            s1 += acc[rt][j][2] + acc[rt][j][3];
            q1 += acc[rt][j][2] * acc[rt][j][2] + acc[rt][j][3] * acc[rt][j][3];
        }
#pragma unroll
        for (int m = 1; m <= 2; m <<= 1) {
            s0 += __shfl_xor_sync(0xffffffffu, s0, m);
            q0 += __shfl_xor_sync(0xffffffffu, q0, m);
            s1 += __shfl_xor_sync(0xffffffffu, s1, m);
            q1 += __shfl_xor_sync(0xffffffffu, q1, m);
        }
        if (tg == 0) {
            int r0 = rowbase + rt * 16 + gid;
            psum[r0][cg]     = make_float2(s0, q0);
            psum[r0 + 8][cg] = make_float2(s1, q1);
        }
    }
    __syncthreads();

    // ---- LN in registers + direct float2 stores to gmem ----
    size_t obase = (size_t)node0 * KNN * ED;
#pragma unroll
    for (int rt = 0; rt < 3; rt++) {
        int r0 = rowbase + rt * 16 + gid;
        float2 pa0 = psum[r0][0], pa1 = psum[r0][1];
        float2 pa2 = psum[r0][2], pa3 = psum[r0][3];
        float2 pb0 = psum[r0 + 8][0], pb1 = psum[r0 + 8][1];
        float2 pb2 = psum[r0 + 8][2], pb3 = psum[r0 + 8][3];
        float mean0 = (pa0.x + pa1.x + pa2.x + pa3.x) * (1.0f / 128.0f);
        float var0  = (pa0.y + pa1.y + pa2.y + pa3.y) * (1.0f / 128.0f) - mean0 * mean0;
        float rs0   = rsqrtf(var0 + 1e-5f);
        float mean1 = (pb0.x + pb1.x + pb2.x + pb3.x) * (1.0f / 128.0f);
        float var1  = (pb0.y + pb1.y + pb2.y + pb3.y) * (1.0f / 128.0f) - mean1 * mean1;
        float rs1   = rsqrtf(var1 + 1e-5f);
        float* dst0 = outE + obase + (size_t)r0 * ED;
        float* dst1 = dst0 + 8 * ED;
#pragma unroll
        for (int j = 0; j < 4; j++) {
            int col = colbase + j * 8 + 2 * tg;
            float g0 = gam[col], g1 = gam[col + 1];
            float b0 = bet[col], b1 = bet[col + 1];
            *(float2*)(dst0 + col) =
                make_float2((acc[rt][j][0] - mean0) * rs0 * g0 + b0,
                            (acc[rt][j][1] - mean0) * rs0 * g1 + b1);
            *(float2*)(dst1 + col) =
                make_float2((acc[rt][j][2] - mean1) * rs1 * g0 + b0,
                            (acc[rt][j][3] - mean1) * rs1 * g1 + b1);
        }
    }
}

// ---------------------------------------------------------------------------
extern "C" void kernel_launch(void* const* d_in, const int* in_sizes, int n_in,
                              void* d_out, int out_size) {
    const float* X     = (const float*)d_in[0];
    const float* mask  = (const float*)d_in[1];
    const int*   ridx  = (const int*)d_in[2];
    const int*   chain = (const int*)d_in[3];
    const float* Wpos  = (const float*)d_in[4];
    const float* bpos  = (const float*)d_in[5];
    const float* Wedge = (const float*)d_in[6];
    const float* gam   = (const float*)d_in[7];
    const float* bet   = (const float*)d_in[8];

    float* outE = (float*)d_out;
    size_t nE = (size_t)BB * LL * KNN * ED;
    float* outI = ((size_t)out_size > nE) ? (outE + nE) : nullptr;

    prep_kernel<<<16 + (208 * ED + 255) / 256, 256>>>(X, mask, Wedge);
    topk_kernel<<<BB * LL, 256>>>(outI);

    static const int smemK3 = DSMW * 4;   // 49152 B (pipeline only)
    cudaFuncSetAttribute(edge_kernel,
                         cudaFuncAttributeMaxDynamicSharedMemorySize, smemK3);
    edge_kernel<<<BB * LL / 2, 256, smemK3>>>(ridx, chain, Wpos, bpos,
                                              gam, bet, outE);
    (void)in_sizes; (void)n_in;
}

// round 16
// speedup vs baseline: 1.0965x; 1.0833x over previous
#include <cuda_runtime.h>
#include <cuda_fp16.h>
#include <cstdint>

#define BB   2
#define LL   2048
#define KNN  48
#define ED   128
#define NCH  13            // 13 K-chunks of 32 fp32 cols = K=416

#define ASTR 20            // A smem row stride in u32 (16 half2 + 4 pad)
#define WSTR 132           // W smem row stride in u32 (128 + 4 pad)
#define AWRD (96 * ASTR)   // words per A stage = 1920
#define WWRD (16 * WSTR)   // words per W stage = 2112 (16 k-pair rows)
#define DSMW (2 * AWRD + 4 * WWRD)   // 12288 words = 49152 B

// scratch (allocation-free rule: __device__ globals)
__device__ float    g_atoms[BB * LL * 15];
__device__ float4   g_ca[BB * LL];    // packed (Ca.xyz, mask) for topk
__device__ int      g_eidx[BB * LL * KNN];
__device__ unsigned g_Wh[208 * ED];   // W as half2 k-pairs: [k/2][n]

__device__ __forceinline__ unsigned smem_u32(const void* p) {
    unsigned a;
    asm("{ .reg .u64 t; cvta.to.shared.u64 t, %1; cvt.u32.u64 %0, t; }"
        : "=r"(a) : "l"(p));
    return a;
}
__device__ __forceinline__ void cp16(unsigned dst, const void* src) {
    asm volatile("cp.async.cg.shared.global [%0], [%1], 16;" :: "r"(dst), "l"(src));
}
__device__ __forceinline__ void cp_commit() {
    asm volatile("cp.async.commit_group;" ::: "memory");
}
__device__ __forceinline__ void cp_wait2() {
    asm volatile("cp.async.wait_group 2;" ::: "memory");
}
__device__ __forceinline__ unsigned packh2(float a, float b) {
    __half2 h = __floats2half2_rn(a, b);
    return *(unsigned*)&h;
}
__device__ __forceinline__ void ldmA(unsigned* a, unsigned addr) {
    asm volatile(
        "ldmatrix.sync.aligned.m8n8.x4.shared.b16 {%0,%1,%2,%3}, [%4];"
        : "=r"(a[0]), "=r"(a[1]), "=r"(a[2]), "=r"(a[3]) : "r"(addr));
}

#define MMA_F16(d, a, b)                                                      \
    asm volatile(                                                             \
        "mma.sync.aligned.m16n8k16.row.col.f32.f16.f16.f32 "                  \
        "{%0,%1,%2,%3}, {%4,%5,%6,%7}, {%8,%9}, {%0,%1,%2,%3};"               \
        : "+f"(d[0]), "+f"(d[1]), "+f"(d[2]), "+f"(d[3])                      \
        : "r"(a[0]), "r"(a[1]), "r"(a[2]), "r"(a[3]), "r"(b[0]), "r"(b[1]))

// ---------------------------------------------------------------------------
// Kernel 0 (merged prep): blocks 0..15 build atoms + packed (Ca,mask);
// blocks 16+ pack W into half2 k-pairs g_Wh[kk][n] (k-major rows).
// ---------------------------------------------------------------------------
__global__ void prep_kernel(const float* __restrict__ X,
                            const float* __restrict__ mask,
                            const float* __restrict__ W) {
    if (blockIdx.x < 16) {
        int idx = blockIdx.x * 256 + threadIdx.x;
        if (idx >= BB * LL) return;
        const float* x = X + (size_t)idx * 12;
        float Nx = x[0],  Ny = x[1],  Nz = x[2];
        float Cax = x[3], Cay = x[4], Caz = x[5];
        float Cx = x[6],  Cy = x[7],  Cz = x[8];
        float Ox = x[9],  Oy = x[10], Oz = x[11];

        float bx = Cax - Nx,  by = Cay - Ny,  bz = Caz - Nz;
        float cx = Cx - Cax,  cy = Cy - Cay,  cz = Cz - Caz;
        float ax = by * cz - bz * cy;
        float ay = bz * cx - bx * cz;
        float az = bx * cy - by * cx;
        float Cbx = -0.58273431f * ax + 0.56802827f * bx - 0.54067466f * cx + Cax;
        float Cby = -0.58273431f * ay + 0.56802827f * by - 0.54067466f * cy + Cay;
        float Cbz = -0.58273431f * az + 0.56802827f * bz - 0.54067466f * cz + Caz;

        float* o = g_atoms + (size_t)idx * 15;
        o[0]  = Cax; o[1]  = Cay; o[2]  = Caz;
        o[3]  = Nx;  o[4]  = Ny;  o[5]  = Nz;
        o[6]  = Cx;  o[7]  = Cy;  o[8]  = Cz;
        o[9]  = Ox;  o[10] = Oy;  o[11] = Oz;
        o[12] = Cbx; o[13] = Cby; o[14] = Cbz;
        g_ca[idx] = make_float4(Cax, Cay, Caz, mask[idx]);
    } else {
        int idx = (blockIdx.x - 16) * 256 + threadIdx.x;
        if (idx >= 208 * ED) return;
        int kk = idx / ED, n = idx % ED;
        g_Wh[idx] = packh2(W[(2 * kk) * ED + n], W[(2 * kk + 1) * ED + n]);
    }
}

// ---------------------------------------------------------------------------
// Radix-select helper (warp 0 scans hist[256] for pivot crossing thr)
// ---------------------------------------------------------------------------
__device__ __forceinline__ void scan_pivot(const unsigned* hist, unsigned thr,
                                           unsigned* s_pivot, unsigned* s_base,
                                           int tid) {
    if (tid < 32) {
        unsigned v[8], pre[8], s = 0;
#pragma unroll
        for (int j = 0; j < 8; j++) { v[j] = hist[tid * 8 + j]; pre[j] = s; s += v[j]; }
        unsigned tot = s, x = tot;
#pragma unroll
        for (int off = 1; off < 32; off <<= 1) {
            unsigned y = __shfl_up_sync(0xffffffffu, x, off);
            if (tid >= off) x += y;
        }
        unsigned ex = x - tot;
        if (ex < thr && ex + tot >= thr) {
#pragma unroll
            for (int j = 0; j < 8; j++) {
                unsigned cb = ex + pre[j];
                if (cb < thr && cb + v[j] >= thr) { *s_pivot = tid * 8 + j; *s_base = cb; }
            }
        }
    }
}

// ---------------------------------------------------------------------------
// Kernel 2 (R13 best version): top-K. Selection on squared distances
// (FMA only); smallest-64 radix superset -> exact sqrt on 64 finalists ->
// exact bitonic sort (bit-identical E_idx). One row per block.
// ---------------------------------------------------------------------------
__global__ void __launch_bounds__(256) topk_kernel(float* __restrict__ outI) {
    __shared__ __align__(16) char sbuf[32768];
    float* cxs = (float*)sbuf;
    float* cys = cxs + LL;
    float* czs = cys + LL;
    float* mms = czs + LL;
    unsigned long long* cand1 = (unsigned long long*)sbuf;            // 16KB
    unsigned long long* cand2 = (unsigned long long*)(sbuf + 16384);  // 16KB
    __shared__ unsigned hist[256];
    __shared__ unsigned long long win[64];
    __shared__ unsigned s_nwin, s_nc1, s_nc2, s_pivot, s_base;
    __shared__ float wmaxs[8];
    __shared__ float s_dmx;

    const unsigned INF_BITS = 0x7F800000u;

    int b   = blockIdx.x >> 11;
    int i   = blockIdx.x & (LL - 1);
    int tid = threadIdx.x;
    int lane = tid & 31, wid = tid >> 5;

    for (int t = tid; t < LL; t += 256) {
        float4 v = g_ca[b * LL + t];
        cxs[t] = v.x; cys[t] = v.y; czs[t] = v.z; mms[t] = v.w;
    }
    __syncthreads();

    float xi = cxs[i], yi = cys[i], zi = czs[i], mi = mms[i];
    unsigned long long k[8];
    float smax = -1.0f;           // max squared dist over unmasked entries
#pragma unroll
    for (int u = 0; u < 8; u++) {
        int j = tid * 8 + u;
        // exact fp32 op order, no fma-contraction (matches XLA up to sqrt)
        float dx = __fsub_rn(cxs[j], xi);
        float dy = __fsub_rn(cys[j], yi);
        float dz = __fsub_rn(czs[j], zi);
        float s  = __fadd_rn(__fadd_rn(__fmul_rn(dx, dx), __fmul_rn(dy, dy)),
                             __fmul_rn(dz, dz));
        float mij = __fmul_rn(mi, mms[j]);
        bool masked = (mij == 0.0f);
        if (!masked) smax = fmaxf(smax, s);
        unsigned sbits = masked ? INF_BITS : __float_as_uint(s);
        k[u] = ((unsigned long long)sbits << 32) | (unsigned)j;
    }
#pragma unroll
    for (int off = 16; off > 0; off >>= 1)
        smax = fmaxf(smax, __shfl_xor_sync(0xffffffffu, smax, off));
    if (lane == 0) wmaxs[wid] = smax;
    __syncthreads();
    if (tid == 0) {
        float m = wmaxs[0];
        for (int w = 1; w < 8; w++) m = fmaxf(m, wmaxs[w]);
        s_dmx = (m >= 0.0f) ? __fsqrt_rn(__fadd_rn(m, 1e-6f)) : 0.0f;
    }
    __syncthreads();   // done reading coordinate smem; safe to alias as cand*

    // ---- level 1: histogram on key bits [63:56], threshold 64 ----
    hist[tid] = 0;
    if (tid == 0) { s_nwin = 0; s_nc1 = 0; s_nc2 = 0; }
    __syncthreads();
#pragma unroll
    for (int u = 0; u < 8; u++)
        atomicAdd(&hist[(unsigned)(k[u] >> 56)], 1u);
    __syncthreads();
    scan_pivot(hist, 64u, &s_pivot, &s_base, tid);
    __syncthreads();
    unsigned p1 = s_pivot, base1 = s_base;
#pragma unroll
    for (int u = 0; u < 8; u++) {
        unsigned bn = (unsigned)(k[u] >> 56);
        if (bn < p1)       win[atomicAdd(&s_nwin, 1u)]   = k[u];
        else if (bn == p1) cand1[atomicAdd(&s_nc1, 1u)]  = k[u];
    }
    __syncthreads();

    // ---- level 2: histogram on key bits [55:48] within pivot bin ----
    unsigned need = 64u - base1;
    hist[tid] = 0;
    __syncthreads();
    unsigned nc1 = s_nc1;
    for (unsigned t = tid; t < nc1; t += 256)
        atomicAdd(&hist[(unsigned)(cand1[t] >> 48) & 255u], 1u);
    __syncthreads();
    scan_pivot(hist, need, &s_pivot, &s_base, tid);
    __syncthreads();
    unsigned p2 = s_pivot;
    for (unsigned t = tid; t < nc1; t += 256) {
        unsigned long long v = cand1[t];
        unsigned bn = (unsigned)(v >> 48) & 255u;
        if (bn < p2)       win[atomicAdd(&s_nwin, 1u)]  = v;
        else if (bn == p2) cand2[atomicAdd(&s_nc2, 1u)] = v;
    }
    __syncthreads();

    // ---- exact extraction of remaining finalists (to 64) from cand2 ----
    if (wid == 0) {
        int m2 = (int)s_nc2;
        int nw = (int)s_nwin;
        int rem = 64 - nw;        // >= 1 by construction
        for (int r = 0; r < rem; r++) {
            unsigned long long best = ~0ull; int bp = -1;
            for (int t = lane; t < m2; t += 32) {
                unsigned long long v = cand2[t];
                if (v < best) { best = v; bp = t; }
            }
#pragma unroll
            for (int off = 16; off > 0; off >>= 1) {
                unsigned long long o = __shfl_xor_sync(0xffffffffu, best, off);
                int op = __shfl_xor_sync(0xffffffffu, bp, off);
                if (o < best) { best = o; bp = op; }
            }
            if (lane == 0) { win[nw + r] = best; cand2[bp] = ~0ull; }
            __syncwarp();
        }
    }
    __syncthreads();

    // ---- finalize: exact adj keys for the 64 finalists (64 sqrts total) ----
    if (tid < 64) {
        unsigned long long v = win[tid];
        unsigned sbits = (unsigned)(v >> 32);
        float adj;
        if (sbits == INF_BITS) {
            adj = s_dmx;   // masked: dv=0, (1-m2)=1 -> adj = dmax exactly
        } else {
            float s  = __uint_as_float(sbits);
            adj = __fsqrt_rn(__fadd_rn(s, 1e-6f));
        }
        win[tid] = ((unsigned long long)__float_as_uint(adj) << 32) |
                   (v & 0xffffffffull);
    }
    __syncthreads();

    // ---- exact bitonic sort of the 64 final keys, warp 0; emit first 48 ----
    if (wid == 0) {
        unsigned long long a0 = win[2 * lane], a1 = win[2 * lane + 1];
#pragma unroll
        for (int kk = 2; kk <= 64; kk <<= 1) {
#pragma unroll
            for (int j = kk >> 1; j >= 1; j >>= 1) {
                bool up = ((2 * lane) & kk) == 0;
                if (j == 1) {
                    if (up ? (a0 > a1) : (a0 < a1)) {
                        unsigned long long t = a0; a0 = a1; a1 = t;
                    }
                } else {
                    int d = j >> 1;
                    bool lower = (lane & d) == 0;
                    unsigned long long q0 = __shfl_xor_sync(0xffffffffu, a0, d);
                    unsigned long long q1 = __shfl_xor_sync(0xffffffffu, a1, d);
                    bool keepmin = (up == lower);
                    a0 = keepmin ? (a0 < q0 ? a0 : q0) : (a0 > q0 ? a0 : q0);
                    a1 = keepmin ? (a1 < q1 ? a1 : q1) : (a1 > q1 ? a1 : q1);
                }
            }
        }
        size_t baseo = (size_t)(b * LL + i) * KNN;
        int r0 = 2 * lane, r1 = 2 * lane + 1;
        if (r0 < KNN) {
            int j = (int)(unsigned)(a0 & 0xffffffffull);
            g_eidx[baseo + r0] = j;
            if (outI) outI[baseo + r0] = (float)j;
        }
        if (r1 < KNN) {
            int j = (int)(unsigned)(a1 & 0xffffffffull);
            g_eidx[baseo + r1] = j;
            if (outI) outI[baseo + r1] = (float)j;
        }
    }
}

// ---------------------------------------------------------------------------
// Kernel 3 (hot, R13 best version): 2 nodes per CTA (96x128). fp16 m16n8k16
// MMA (fp32 accum). A via ldmatrix.x4, B scalar LDS, direct-store LN
// epilogue, 3 CTAs/SM. Unconditional __expf (predication experiment reverted).
// ---------------------------------------------------------------------------
__global__ void __launch_bounds__(256, 3) edge_kernel(
    const int* __restrict__ ridx, const int* __restrict__ chain,
    const float* __restrict__ Wpos, const float* __restrict__ bpos,
    const float* __restrict__ gamma_, const float* __restrict__ beta_,
    float* __restrict__ outE) {
    extern __shared__ unsigned dsm[];
    __shared__ float ssat[2 * 15];
    __shared__ float snat[96 * 15];
    __shared__ float gam[ED], bet[ED];
    __shared__ float bposs[16];
    __shared__ int   eidx_s[96];
    __shared__ int   dcls[96];
    __shared__ float2 psum[96][4];     // per-(row, colgroup) partial (sum, sumsq)

    int tid  = threadIdx.x;
    int wid  = tid >> 5;
    int lane = tid & 31;
    int gid  = lane >> 2, tg = lane & 3;
    int node0 = 2 * blockIdx.x;
    int b = node0 >> 11;

    unsigned smA = smem_u32(dsm);
    unsigned smW = smA + 2 * AWRD * 4;

    if (tid < ED) { gam[tid] = gamma_[tid]; bet[tid] = beta_[tid]; }
    if (tid < 16) bposs[tid] = bpos[tid];
    if (tid < 96) eidx_s[tid] = g_eidx[(size_t)node0 * KNN + tid];
    if (tid >= 128 && tid < 158) ssat[tid - 128] = g_atoms[(size_t)node0 * 15 + (tid - 128)];
    __syncthreads();

    if (tid < 96) {
        int nl = tid / KNN;
        int j  = eidx_s[tid];
        int ng = node0 + nl;
        int off  = ridx[ng] - ridx[b * LL + j];
        int same = (chain[ng] == chain[b * LL + j]);
        int d = off + 32;
        d = d < 0 ? 0 : (d > 64 ? 64 : d);
        dcls[tid] = same ? d : 65;
    }
    for (int t = tid; t < 96 * 15; t += 256) {
        int n = t / 15, c = t % 15;
        snat[t] = g_atoms[(size_t)(b * LL + eidx_s[n]) * 15 + c];
    }

    // prologue: W chunks 0,1 into ring stages 0,1 (8KB each, 2 cp16/thread)
#pragma unroll
    for (int q = 0; q < 2; q++) {
        unsigned bst = smW + (unsigned)(q & 3) * WWRD * 4;
#pragma unroll
        for (int e = 0; e < 2; e++) {
            int idx = tid + e * 256;            // 0..511
            int r = idx >> 5, g = idx & 31;     // k-pair row 0..15, granule 0..31
            cp16(bst + (unsigned)(r * WSTR + g * 4) * 4,
                 g_Wh + (size_t)(q * 16 + r) * ED + g * 4);
        }
        cp_commit();
    }
    __syncthreads();   // snat/ssat/dcls visible before feature compute

    // prologue: features chunk 0 (positional + pair 0) into A stage 0
    {
        uint4* Ab = (uint4*)dsm;
        if (tid < 96) {
            int row = tid, dc = dcls[row];
            unsigned w[8];
#pragma unroll
            for (int q = 0; q < 8; q++)
                w[q] = packh2(Wpos[dc * 16 + 2 * q]     + bposs[2 * q],
                              Wpos[dc * 16 + 2 * q + 1] + bposs[2 * q + 1]);
            Ab[(row * ASTR) >> 2]       = make_uint4(w[0], w[1], w[2], w[3]);
            Ab[(row * ASTR + 4) >> 2]   = make_uint4(w[4], w[5], w[6], w[7]);
        } else if (tid < 192) {
            int row = tid - 96;                 // pair 0 (Ca-Ca)
            int nl = row / KNN;
            float dx = ssat[nl * 15 + 0] - snat[row * 15 + 0];
            float dy = ssat[nl * 15 + 1] - snat[row * 15 + 1];
            float dz = ssat[nl * 15 + 2] - snat[row * 15 + 2];
            float Dp = sqrtf(dx * dx + dy * dy + dz * dz + 1e-6f);
            unsigned w[8];
#pragma unroll
            for (int q = 0; q < 8; q++) {
                float mu0 = 2.0f + (20.0f / 15.0f) * (float)(2 * q);
                float mu1 = 2.0f + (20.0f / 15.0f) * (float)(2 * q + 1);
                float z0 = (Dp - mu0) * 0.8f, z1 = (Dp - mu1) * 0.8f;
                w[q] = packh2(__expf(-z0 * z0), __expf(-z1 * z1));
            }
            Ab[(row * ASTR + 8) >> 2]   = make_uint4(w[0], w[1], w[2], w[3]);
            Ab[(row * ASTR + 12) >> 2]  = make_uint4(w[4], w[5], w[6], w[7]);
        }
    }

    float acc[3][4][4];
#pragma unroll
    for (int rt = 0; rt < 3; rt++)
#pragma unroll
        for (int j = 0; j < 4; j++)
#pragma unroll
            for (int c = 0; c < 4; c++) acc[rt][j][c] = 0.0f;

    int rg = wid >> 2, cg = wid & 3;
    int rowbase = rg * 48;
    int colbase = cg * 32;
    // ldmatrix lane address component: row = rowbase + (lane&15), koff = (lane>>4)*4
    unsigned lmBase = (unsigned)(((rowbase + (lane & 15)) * ASTR + ((lane >> 4) << 2)) * 4);

    for (int c = 0; c < NCH; c++) {
        // ---- issue W chunk c+2 into ring stage (c+2)&3 ----
        if (c + 2 < NCH) {
            int q = c + 2;
            unsigned bst = smW + (unsigned)(q & 3) * WWRD * 4;
#pragma unroll
            for (int e = 0; e < 2; e++) {
                int idx = tid + e * 256;
                int r = idx >> 5, g = idx & 31;
                cp16(bst + (unsigned)(r * WSTR + g * 4) * 4,
                     g_Wh + (size_t)(q * 16 + r) * ED + g * 4);
            }
        }
        cp_commit();
        cp_wait2();              // W chunk c landed
        __syncthreads();         // A(c) features + W(c) visible; orders
                                 // MMA(c-1) reads before features(c+1) writes

        // ---- MMA on chunk c: 2 k16 steps (reads A[c&1], W[c&3]) ----
        unsigned aBase = smA + (unsigned)((c & 1) * AWRD * 4) + lmBase;
        unsigned* Wb = dsm + 2 * AWRD + (c & 3) * WWRD;
#pragma unroll
        for (int s = 0; s < 2; s++) {
            int kb = s * 8;      // u32 (half2) column base
            unsigned a[3][4];
#pragma unroll
            for (int rt = 0; rt < 3; rt++)
                ldmA(a[rt], aBase + (unsigned)((rt * 16 * ASTR + kb) * 4));
            unsigned bf[4][2];
#pragma unroll
            for (int j = 0; j < 4; j++) {
                bf[j][0] = Wb[(kb + tg) * WSTR + colbase + j * 8 + gid];
                bf[j][1] = Wb[(kb + tg + 4) * WSTR + colbase + j * 8 + gid];
            }
#pragma unroll
            for (int rt = 0; rt < 3; rt++)
#pragma unroll
                for (int j = 0; j < 4; j++)
                    MMA_F16(acc[rt][j], a[rt], bf[j]);
        }

        // ---- overlap: compute features chunk c+1 into A[(c+1)&1] ----
        if (c + 1 < NCH && tid < 192) {
            uint4* An = (uint4*)(dsm + ((c + 1) & 1) * AWRD);
            int pi = tid / 96, row = tid % 96;
            int nl = row / KNN;
            int p  = 2 * (c + 1) - 1 + pi;         // pair 1..24
            int a1 = p / 5, a2 = p % 5;
            float dx = ssat[nl * 15 + a1 * 3 + 0] - snat[row * 15 + a2 * 3 + 0];
            float dy = ssat[nl * 15 + a1 * 3 + 1] - snat[row * 15 + a2 * 3 + 1];
            float dz = ssat[nl * 15 + a1 * 3 + 2] - snat[row * 15 + a2 * 3 + 2];
            float Dp = sqrtf(dx * dx + dy * dy + dz * dz + 1e-6f);
            int cb = 8 * pi;
            unsigned w[8];
#pragma unroll
            for (int q = 0; q < 8; q++) {
                float mu0 = 2.0f + (20.0f / 15.0f) * (float)(2 * q);
                float mu1 = 2.0f + (20.0f / 15.0f) * (float)(2 * q + 1);
                float z0 = (Dp - mu0) * 0.8f, z1 = (Dp - mu1) * 0.8f;
                w[q] = packh2(__expf(-z0 * z0), __expf(-z1 * z1));
            }
            An[(row * ASTR + cb) >> 2]     = make_uint4(w[0], w[1], w[2], w[3]);
            An[(row * ASTR + cb + 4) >> 2] = make_uint4(w[4], w[5], w[6], w[7]);
        }
    }

    // ---- epilogue: per-row partials across the 4 colgroup warps ----
#pragma unroll
    for (int rt = 0; rt < 3; rt++) {
        float s0 = 0.f, q0 = 0.f, s1 = 0.f, q1 = 0.f;
#pragma unroll
        for (int j = 0; j < 4; j++) {
            s0 += acc[rt][j][0] + acc[rt][j][1];
            q0 += acc[rt][j][0] * acc[rt][j][0] + acc[rt][j][1] * acc[rt][j][1];
            s1 += acc[rt][j][2] + acc[rt][j][3];
            q1 += acc[rt][j][2] * acc[rt][j][2] + acc[rt][j][3] * acc[rt][j][3];
        }
#pragma unroll
        for (int m = 1; m <= 2; m <<= 1) {
            s0 += __shfl_xor_sync(0xffffffffu, s0, m);
            q0 += __shfl_xor_sync(0xffffffffu, q0, m);
            s1 += __shfl_xor_sync(0xffffffffu, s1, m);
            q1 += __shfl_xor_sync(0xffffffffu, q1, m);
        }
        if (tg == 0) {
            int r0 = rowbase + rt * 16 + gid;
            psum[r0][cg]     = make_float2(s0, q0);
            psum[r0 + 8][cg] = make_float2(s1, q1);
        }
    }
    __syncthreads();

    // ---- LN in registers + direct float2 stores to gmem ----
    size_t obase = (size_t)node0 * KNN * ED;
#pragma unroll
    for (int rt = 0; rt < 3; rt++) {
        int r0 = rowbase + rt * 16 + gid;
        float2 pa0 = psum[r0][0], pa1 = psum[r0][1];
        float2 pa2 = psum[r0][2], pa3 = psum[r0][3];
        float2 pb0 = psum[r0 + 8][0], pb1 = psum[r0 + 8][1];
        float2 pb2 = psum[r0 + 8][2], pb3 = psum[r0 + 8][3];
        float mean0 = (pa0.x + pa1.x + pa2.x + pa3.x) * (1.0f / 128.0f);
        float var0  = (pa0.y + pa1.y + pa2.y + pa3.y) * (1.0f / 128.0f) - mean0 * mean0;
        float rs0   = rsqrtf(var0 + 1e-5f);
        float mean1 = (pb0.x + pb1.x + pb2.x + pb3.x) * (1.0f / 128.0f);
        float var1  = (pb0.y + pb1.y + pb2.y + pb3.y) * (1.0f / 128.0f) - mean1 * mean1;
        float rs1   = rsqrtf(var1 + 1e-5f);
        float* dst0 = outE + obase + (size_t)r0 * ED;
        float* dst1 = dst0 + 8 * ED;
#pragma unroll
        for (int j = 0; j < 4; j++) {
            int col = colbase + j * 8 + 2 * tg;
            float g0 = gam[col], g1 = gam[col + 1];
            float b0 = bet[col], b1 = bet[col + 1];
            *(float2*)(dst0 + col) =
                make_float2((acc[rt][j][0] - mean0) * rs0 * g0 + b0,
                            (acc[rt][j][1] - mean0) * rs0 * g1 + b1);
            *(float2*)(dst1 + col) =
                make_float2((acc[rt][j][2] - mean1) * rs1 * g0 + b0,
                            (acc[rt][j][3] - mean1) * rs1 * g1 + b1);
        }
    }
}

// ---------------------------------------------------------------------------
extern "C" void kernel_launch(void* const* d_in, const int* in_sizes, int n_in,
                              void* d_out, int out_size) {
    const float* X     = (const float*)d_in[0];
    const float* mask  = (const float*)d_in[1];
    const int*   ridx  = (const int*)d_in[2];
    const int*   chain = (const int*)d_in[3];
    const float* Wpos  = (const float*)d_in[4];
    const float* bpos  = (const float*)d_in[5];
    const float* Wedge = (const float*)d_in[6];
    const float* gam   = (const float*)d_in[7];
    const float* bet   = (const float*)d_in[8];

    float* outE = (float*)d_out;
    size_t nE = (size_t)BB * LL * KNN * ED;
    float* outI = ((size_t)out_size > nE) ? (outE + nE) : nullptr;

    prep_kernel<<<16 + (208 * ED + 255) / 256, 256>>>(X, mask, Wedge);
    topk_kernel<<<BB * LL, 256>>>(outI);

    static const int smemK3 = DSMW * 4;   // 49152 B (pipeline only)
    cudaFuncSetAttribute(edge_kernel,
                         cudaFuncAttributeMaxDynamicSharedMemorySize, smemK3);
    edge_kernel<<<BB * LL / 2, 256, smemK3>>>(ridx, chain, Wpos, bpos,
                                              gam, bet, outE);
    (void)in_sizes; (void)n_in;
}

// round 17
// speedup vs baseline: 1.1110x; 1.0132x over previous
#include <cuda_runtime.h>
#include <cuda_fp16.h>
#include <cstdint>

#define BB   2
#define LL   2048
#define KNN  48
#define ED   128
#define NCH  13            // 13 K-chunks of 32 fp32 cols = K=416

#define ASTR 20            // A smem row stride in u32 (16 half2 + 4 pad)
#define WSTR 132           // W smem row stride in u32 (128 + 4 pad)
#define AWRD (96 * ASTR)   // words per A stage = 1920
#define WWRD (16 * WSTR)   // words per W stage = 2112 (16 k-pair rows)
#define DSMW (2 * AWRD + 4 * WWRD)   // 12288 words = 49152 B

// scratch (allocation-free rule: __device__ globals)
__device__ float    g_atoms[BB * LL * 15];
__device__ float4   g_ca[BB * LL];    // packed (Ca.xyz, mask) for topk
__device__ int      g_eidx[BB * LL * KNN];
__device__ unsigned g_Wh[208 * ED];   // W as half2 k-pairs: [k/2][n]

__device__ __forceinline__ unsigned smem_u32(const void* p) {
    unsigned a;
    asm("{ .reg .u64 t; cvta.to.shared.u64 t, %1; cvt.u32.u64 %0, t; }"
        : "=r"(a) : "l"(p));
    return a;
}
__device__ __forceinline__ void cp16(unsigned dst, const void* src) {
    asm volatile("cp.async.cg.shared.global [%0], [%1], 16;" :: "r"(dst), "l"(src));
}
__device__ __forceinline__ void cp_commit() {
    asm volatile("cp.async.commit_group;" ::: "memory");
}
__device__ __forceinline__ void cp_wait2() {
    asm volatile("cp.async.wait_group 2;" ::: "memory");
}
__device__ __forceinline__ unsigned packh2(float a, float b) {
    __half2 h = __floats2half2_rn(a, b);
    return *(unsigned*)&h;
}
__device__ __forceinline__ void ldmA(unsigned* a, unsigned addr) {
    asm volatile(
        "ldmatrix.sync.aligned.m8n8.x4.shared.b16 {%0,%1,%2,%3}, [%4];"
        : "=r"(a[0]), "=r"(a[1]), "=r"(a[2]), "=r"(a[3]) : "r"(addr));
}

#define MMA_F16(d, a, b)                                                      \
    asm volatile(                                                             \
        "mma.sync.aligned.m16n8k16.row.col.f32.f16.f16.f32 "                  \
        "{%0,%1,%2,%3}, {%4,%5,%6,%7}, {%8,%9}, {%0,%1,%2,%3};"               \
        : "+f"(d[0]), "+f"(d[1]), "+f"(d[2]), "+f"(d[3])                      \
        : "r"(a[0]), "r"(a[1]), "r"(a[2]), "r"(a[3]), "r"(b[0]), "r"(b[1]))

// ---------------------------------------------------------------------------
// Kernel 0 (merged prep): blocks 0..15 build atoms + packed (Ca,mask);
// blocks 16+ pack W into half2 k-pairs g_Wh[kk][n] (k-major rows).
// ---------------------------------------------------------------------------
__global__ void prep_kernel(const float* __restrict__ X,
                            const float* __restrict__ mask,
                            const float* __restrict__ W) {
    if (blockIdx.x < 16) {
        int idx = blockIdx.x * 256 + threadIdx.x;
        if (idx >= BB * LL) return;
        const float* x = X + (size_t)idx * 12;
        float Nx = x[0],  Ny = x[1],  Nz = x[2];
        float Cax = x[3], Cay = x[4], Caz = x[5];
        float Cx = x[6],  Cy = x[7],  Cz = x[8];
        float Ox = x[9],  Oy = x[10], Oz = x[11];

        float bx = Cax - Nx,  by = Cay - Ny,  bz = Caz - Nz;
        float cx = Cx - Cax,  cy = Cy - Cay,  cz = Cz - Caz;
        float ax = by * cz - bz * cy;
        float ay = bz * cx - bx * cz;
        float az = bx * cy - by * cx;
        float Cbx = -0.58273431f * ax + 0.56802827f * bx - 0.54067466f * cx + Cax;
        float Cby = -0.58273431f * ay + 0.56802827f * by - 0.54067466f * cy + Cay;
        float Cbz = -0.58273431f * az + 0.56802827f * bz - 0.54067466f * cz + Caz;

        float* o = g_atoms + (size_t)idx * 15;
        o[0]  = Cax; o[1]  = Cay; o[2]  = Caz;
        o[3]  = Nx;  o[4]  = Ny;  o[5]  = Nz;
        o[6]  = Cx;  o[7]  = Cy;  o[8]  = Cz;
        o[9]  = Ox;  o[10] = Oy;  o[11] = Oz;
        o[12] = Cbx; o[13] = Cby; o[14] = Cbz;
        g_ca[idx] = make_float4(Cax, Cay, Caz, mask[idx]);
    } else {
        int idx = (blockIdx.x - 16) * 256 + threadIdx.x;
        if (idx >= 208 * ED) return;
        int kk = idx / ED, n = idx % ED;
        g_Wh[idx] = packh2(W[(2 * kk) * ED + n], W[(2 * kk + 1) * ED + n]);
    }
}

// ---------------------------------------------------------------------------
// Radix-select helper (warp 0 scans hist[256] for pivot crossing thr)
// ---------------------------------------------------------------------------
__device__ __forceinline__ void scan_pivot(const unsigned* hist, unsigned thr,
                                           unsigned* s_pivot, unsigned* s_base,
                                           int tid) {
    if (tid < 32) {
        unsigned v[8], pre[8], s = 0;
#pragma unroll
        for (int j = 0; j < 8; j++) { v[j] = hist[tid * 8 + j]; pre[j] = s; s += v[j]; }
        unsigned tot = s, x = tot;
#pragma unroll
        for (int off = 1; off < 32; off <<= 1) {
            unsigned y = __shfl_up_sync(0xffffffffu, x, off);
            if (tid >= off) x += y;
        }
        unsigned ex = x - tot;
        if (ex < thr && ex + tot >= thr) {
#pragma unroll
            for (int j = 0; j < 8; j++) {
                unsigned cb = ex + pre[j];
                if (cb < thr && cb + v[j] >= thr) { *s_pivot = tid * 8 + j; *s_base = cb; }
            }
        }
    }
}

// ---------------------------------------------------------------------------
// Kernel 2 (R13/R16 logic + rowbase offset): top-K. Selection on squared
// distances (FMA only); smallest-64 radix superset -> exact sqrt on 64
// finalists -> exact bitonic sort (bit-identical E_idx). One row per block.
// ---------------------------------------------------------------------------
__global__ void __launch_bounds__(256) topk_kernel(float* __restrict__ outI,
                                                   int rowbase) {
    __shared__ __align__(16) char sbuf[32768];
    float* cxs = (float*)sbuf;
    float* cys = cxs + LL;
    float* czs = cys + LL;
    float* mms = czs + LL;
    unsigned long long* cand1 = (unsigned long long*)sbuf;            // 16KB
    unsigned long long* cand2 = (unsigned long long*)(sbuf + 16384);  // 16KB
    __shared__ unsigned hist[256];
    __shared__ unsigned long long win[64];
    __shared__ unsigned s_nwin, s_nc1, s_nc2, s_pivot, s_base;
    __shared__ float wmaxs[8];
    __shared__ float s_dmx;

    const unsigned INF_BITS = 0x7F800000u;

    int row = rowbase + blockIdx.x;
    int b   = row >> 11;
    int i   = row & (LL - 1);
    int tid = threadIdx.x;
    int lane = tid & 31, wid = tid >> 5;

    for (int t = tid; t < LL; t += 256) {
        float4 v = g_ca[b * LL + t];
        cxs[t] = v.x; cys[t] = v.y; czs[t] = v.z; mms[t] = v.w;
    }
    __syncthreads();

    float xi = cxs[i], yi = cys[i], zi = czs[i], mi = mms[i];
    unsigned long long k[8];
    float smax = -1.0f;           // max squared dist over unmasked entries
#pragma unroll
    for (int u = 0; u < 8; u++) {
        int j = tid * 8 + u;
        // exact fp32 op order, no fma-contraction (matches XLA up to sqrt)
        float dx = __fsub_rn(cxs[j], xi);
        float dy = __fsub_rn(cys[j], yi);
        float dz = __fsub_rn(czs[j], zi);
        float s  = __fadd_rn(__fadd_rn(__fmul_rn(dx, dx), __fmul_rn(dy, dy)),
                             __fmul_rn(dz, dz));
        float mij = __fmul_rn(mi, mms[j]);
        bool masked = (mij == 0.0f);
        if (!masked) smax = fmaxf(smax, s);
        unsigned sbits = masked ? INF_BITS : __float_as_uint(s);
        k[u] = ((unsigned long long)sbits << 32) | (unsigned)j;
    }
#pragma unroll
    for (int off = 16; off > 0; off >>= 1)
        smax = fmaxf(smax, __shfl_xor_sync(0xffffffffu, smax, off));
    if (lane == 0) wmaxs[wid] = smax;
    __syncthreads();
    if (tid == 0) {
        float m = wmaxs[0];
        for (int w = 1; w < 8; w++) m = fmaxf(m, wmaxs[w]);
        s_dmx = (m >= 0.0f) ? __fsqrt_rn(__fadd_rn(m, 1e-6f)) : 0.0f;
    }
    __syncthreads();   // done reading coordinate smem; safe to alias as cand*

    // ---- level 1: histogram on key bits [63:56], threshold 64 ----
    hist[tid] = 0;
    if (tid == 0) { s_nwin = 0; s_nc1 = 0; s_nc2 = 0; }
    __syncthreads();
#pragma unroll
    for (int u = 0; u < 8; u++)
        atomicAdd(&hist[(unsigned)(k[u] >> 56)], 1u);
    __syncthreads();
    scan_pivot(hist, 64u, &s_pivot, &s_base, tid);
    __syncthreads();
    unsigned p1 = s_pivot, base1 = s_base;
#pragma unroll
    for (int u = 0; u < 8; u++) {
        unsigned bn = (unsigned)(k[u] >> 56);
        if (bn < p1)       win[atomicAdd(&s_nwin, 1u)]   = k[u];
        else if (bn == p1) cand1[atomicAdd(&s_nc1, 1u)]  = k[u];
    }
    __syncthreads();

    // ---- level 2: histogram on key bits [55:48] within pivot bin ----
    unsigned need = 64u - base1;
    hist[tid] = 0;
    __syncthreads();
    unsigned nc1 = s_nc1;
    for (unsigned t = tid; t < nc1; t += 256)
        atomicAdd(&hist[(unsigned)(cand1[t] >> 48) & 255u], 1u);
    __syncthreads();
    scan_pivot(hist, need, &s_pivot, &s_base, tid);
    __syncthreads();
    unsigned p2 = s_pivot;
    for (unsigned t = tid; t < nc1; t += 256) {
        unsigned long long v = cand1[t];
        unsigned bn = (unsigned)(v >> 48) & 255u;
        if (bn < p2)       win[atomicAdd(&s_nwin, 1u)]  = v;
        else if (bn == p2) cand2[atomicAdd(&s_nc2, 1u)] = v;
    }
    __syncthreads();

    // ---- exact extraction of remaining finalists (to 64) from cand2 ----
    if (wid == 0) {
        int m2 = (int)s_nc2;
        int nw = (int)s_nwin;
        int rem = 64 - nw;        // >= 1 by construction
        for (int r = 0; r < rem; r++) {
            unsigned long long best = ~0ull; int bp = -1;
            for (int t = lane; t < m2; t += 32) {
                unsigned long long v = cand2[t];
                if (v < best) { best = v; bp = t; }
            }
#pragma unroll
            for (int off = 16; off > 0; off >>= 1) {
                unsigned long long o = __shfl_xor_sync(0xffffffffu, best, off);
                int op = __shfl_xor_sync(0xffffffffu, bp, off);
                if (o < best) { best = o; bp = op; }
            }
            if (lane == 0) { win[nw + r] = best; cand2[bp] = ~0ull; }
            __syncwarp();
        }
    }
    __syncthreads();

    // ---- finalize: exact adj keys for the 64 finalists (64 sqrts total) ----
    if (tid < 64) {
        unsigned long long v = win[tid];
        unsigned sbits = (unsigned)(v >> 32);
        float adj;
        if (sbits == INF_BITS) {
            adj = s_dmx;   // masked: dv=0, (1-m2)=1 -> adj = dmax exactly
        } else {
            float s  = __uint_as_float(sbits);
            adj = __fsqrt_rn(__fadd_rn(s, 1e-6f));
        }
        win[tid] = ((unsigned long long)__float_as_uint(adj) << 32) |
                   (v & 0xffffffffull);
    }
    __syncthreads();

    // ---- exact bitonic sort of the 64 final keys, warp 0; emit first 48 ----
    if (wid == 0) {
        unsigned long long a0 = win[2 * lane], a1 = win[2 * lane + 1];
#pragma unroll
        for (int kk = 2; kk <= 64; kk <<= 1) {
#pragma unroll
            for (int j = kk >> 1; j >= 1; j >>= 1) {
                bool up = ((2 * lane) & kk) == 0;
                if (j == 1) {
                    if (up ? (a0 > a1) : (a0 < a1)) {
                        unsigned long long t = a0; a0 = a1; a1 = t;
                    }
                } else {
                    int d = j >> 1;
                    bool lower = (lane & d) == 0;
                    unsigned long long q0 = __shfl_xor_sync(0xffffffffu, a0, d);
                    unsigned long long q1 = __shfl_xor_sync(0xffffffffu, a1, d);
                    bool keepmin = (up == lower);
                    a0 = keepmin ? (a0 < q0 ? a0 : q0) : (a0 > q0 ? a0 : q0);
                    a1 = keepmin ? (a1 < q1 ? a1 : q1) : (a1 > q1 ? a1 : q1);
                }
            }
        }
        size_t baseo = (size_t)row * KNN;
        int r0 = 2 * lane, r1 = 2 * lane + 1;
        if (r0 < KNN) {
            int j = (int)(unsigned)(a0 & 0xffffffffull);
            g_eidx[baseo + r0] = j;
            if (outI) outI[baseo + r0] = (float)j;
        }
        if (r1 < KNN) {
            int j = (int)(unsigned)(a1 & 0xffffffffull);
            g_eidx[baseo + r1] = j;
            if (outI) outI[baseo + r1] = (float)j;
        }
    }
}

// ---------------------------------------------------------------------------
// Kernel 3 (hot, R16 logic + pairbase offset): 2 nodes per CTA (96x128).
// fp16 m16n8k16 MMA (fp32 accum). A via ldmatrix.x4, B scalar LDS,
// direct-store LN epilogue, 3 CTAs/SM.
// ---------------------------------------------------------------------------
__global__ void __launch_bounds__(256, 3) edge_kernel(
    const int* __restrict__ ridx, const int* __restrict__ chain,
    const float* __restrict__ Wpos, const float* __restrict__ bpos,
    const float* __restrict__ gamma_, const float* __restrict__ beta_,
    float* __restrict__ outE, int pairbase) {
    extern __shared__ unsigned dsm[];
    __shared__ float ssat[2 * 15];
    __shared__ float snat[96 * 15];
    __shared__ float gam[ED], bet[ED];
    __shared__ float bposs[16];
    __shared__ int   eidx_s[96];
    __shared__ int   dcls[96];
    __shared__ float2 psum[96][4];     // per-(row, colgroup) partial (sum, sumsq)

    int tid  = threadIdx.x;
    int wid  = tid >> 5;
    int lane = tid & 31;
    int gid  = lane >> 2, tg = lane & 3;
    int node0 = 2 * (pairbase + blockIdx.x);
    int b = node0 >> 11;

    unsigned smA = smem_u32(dsm);
    unsigned smW = smA + 2 * AWRD * 4;

    if (tid < ED) { gam[tid] = gamma_[tid]; bet[tid] = beta_[tid]; }
    if (tid < 16) bposs[tid] = bpos[tid];
    if (tid < 96) eidx_s[tid] = g_eidx[(size_t)node0 * KNN + tid];
    if (tid >= 128 && tid < 158) ssat[tid - 128] = g_atoms[(size_t)node0 * 15 + (tid - 128)];
    __syncthreads();

    if (tid < 96) {
        int nl = tid / KNN;
        int j  = eidx_s[tid];
        int ng = node0 + nl;
        int off  = ridx[ng] - ridx[b * LL + j];
        int same = (chain[ng] == chain[b * LL + j]);
        int d = off + 32;
        d = d < 0 ? 0 : (d > 64 ? 64 : d);
        dcls[tid] = same ? d : 65;
    }
    for (int t = tid; t < 96 * 15; t += 256) {
        int n = t / 15, c = t % 15;
        snat[t] = g_atoms[(size_t)(b * LL + eidx_s[n]) * 15 + c];
    }

    // prologue: W chunks 0,1 into ring stages 0,1 (8KB each, 2 cp16/thread)
#pragma unroll
    for (int q = 0; q < 2; q++) {
        unsigned bst = smW + (unsigned)(q & 3) * WWRD * 4;
#pragma unroll
        for (int e = 0; e < 2; e++) {
            int idx = tid + e * 256;            // 0..511
            int r = idx >> 5, g = idx & 31;     // k-pair row 0..15, granule 0..31
            cp16(bst + (unsigned)(r * WSTR + g * 4) * 4,
                 g_Wh + (size_t)(q * 16 + r) * ED + g * 4);
        }
        cp_commit();
    }
    __syncthreads();   // snat/ssat/dcls visible before feature compute

    // prologue: features chunk 0 (positional + pair 0) into A stage 0
    {
        uint4* Ab = (uint4*)dsm;
        if (tid < 96) {
            int row = tid, dc = dcls[row];
            unsigned w[8];
#pragma unroll
            for (int q = 0; q < 8; q++)
                w[q] = packh2(Wpos[dc * 16 + 2 * q]     + bposs[2 * q],
                              Wpos[dc * 16 + 2 * q + 1] + bposs[2 * q + 1]);
            Ab[(row * ASTR) >> 2]       = make_uint4(w[0], w[1], w[2], w[3]);
            Ab[(row * ASTR + 4) >> 2]   = make_uint4(w[4], w[5], w[6], w[7]);
        } else if (tid < 192) {
            int row = tid - 96;                 // pair 0 (Ca-Ca)
            int nl = row / KNN;
            float dx = ssat[nl * 15 + 0] - snat[row * 15 + 0];
            float dy = ssat[nl * 15 + 1] - snat[row * 15 + 1];
            float dz = ssat[nl * 15 + 2] - snat[row * 15 + 2];
            float Dp = sqrtf(dx * dx + dy * dy + dz * dz + 1e-6f);
            unsigned w[8];
#pragma unroll
            for (int q = 0; q < 8; q++) {
                float mu0 = 2.0f + (20.0f / 15.0f) * (float)(2 * q);
                float mu1 = 2.0f + (20.0f / 15.0f) * (float)(2 * q + 1);
                float z0 = (Dp - mu0) * 0.8f, z1 = (Dp - mu1) * 0.8f;
                w[q] = packh2(__expf(-z0 * z0), __expf(-z1 * z1));
            }
            Ab[(row * ASTR + 8) >> 2]   = make_uint4(w[0], w[1], w[2], w[3]);
            Ab[(row * ASTR + 12) >> 2]  = make_uint4(w[4], w[5], w[6], w[7]);
        }
    }

    float acc[3][4][4];
#pragma unroll
    for (int rt = 0; rt < 3; rt++)
#pragma unroll
        for (int j = 0; j < 4; j++)
#pragma unroll
            for (int c = 0; c < 4; c++) acc[rt][j][c] = 0.0f;

    int rg = wid >> 2, cg = wid & 3;
    int rowbase = rg * 48;
    int colbase = cg * 32;
    // ldmatrix lane address component: row = rowbase + (lane&15), koff = (lane>>4)*4
    unsigned lmBase = (unsigned)(((rowbase + (lane & 15)) * ASTR + ((lane >> 4) << 2)) * 4);

    for (int c = 0; c < NCH; c++) {
        // ---- issue W chunk c+2 into ring stage (c+2)&3 ----
        if (c + 2 < NCH) {
            int q = c + 2;
            unsigned bst = smW + (unsigned)(q & 3) * WWRD * 4;
#pragma unroll
            for (int e = 0; e < 2; e++) {
                int idx = tid + e * 256;
                int r = idx >> 5, g = idx & 31;
                cp16(bst + (unsigned)(r * WSTR + g * 4) * 4,
                     g_Wh + (size_t)(q * 16 + r) * ED + g * 4);
            }
        }
        cp_commit();
        cp_wait2();              // W chunk c landed
        __syncthreads();         // A(c) features + W(c) visible; orders
                                 // MMA(c-1) reads before features(c+1) writes

        // ---- MMA on chunk c: 2 k16 steps (reads A[c&1], W[c&3]) ----
        unsigned aBase = smA + (unsigned)((c & 1) * AWRD * 4) + lmBase;
        unsigned* Wb = dsm + 2 * AWRD + (c & 3) * WWRD;
#pragma unroll
        for (int s = 0; s < 2; s++) {
            int kb = s * 8;      // u32 (half2) column base
            unsigned a[3][4];
#pragma unroll
            for (int rt = 0; rt < 3; rt++)
                ldmA(a[rt], aBase + (unsigned)((rt * 16 * ASTR + kb) * 4));
            unsigned bf[4][2];
#pragma unroll
            for (int j = 0; j < 4; j++) {
                bf[j][0] = Wb[(kb + tg) * WSTR + colbase + j * 8 + gid];
                bf[j][1] = Wb[(kb + tg + 4) * WSTR + colbase + j * 8 + gid];
            }
#pragma unroll
            for (int rt = 0; rt < 3; rt++)
#pragma unroll
                for (int j = 0; j < 4; j++)
                    MMA_F16(acc[rt][j], a[rt], bf[j]);
        }

        // ---- overlap: compute features chunk c+1 into A[(c+1)&1] ----
        if (c + 1 < NCH && tid < 192) {
            uint4* An = (uint4*)(dsm + ((c + 1) & 1) * AWRD);
            int pi = tid / 96, row = tid % 96;
            int nl = row / KNN;
            int p  = 2 * (c + 1) - 1 + pi;         // pair 1..24
            int a1 = p / 5, a2 = p % 5;
            float dx = ssat[nl * 15 + a1 * 3 + 0] - snat[row * 15 + a2 * 3 + 0];
            float dy = ssat[nl * 15 + a1 * 3 + 1] - snat[row * 15 + a2 * 3 + 1];
            float dz = ssat[nl * 15 + a1 * 3 + 2] - snat[row * 15 + a2 * 3 + 2];
            float Dp = sqrtf(dx * dx + dy * dy + dz * dz + 1e-6f);
            int cb = 8 * pi;
            unsigned w[8];
#pragma unroll
            for (int q = 0; q < 8; q++) {
                float mu0 = 2.0f + (20.0f / 15.0f) * (float)(2 * q);
                float mu1 = 2.0f + (20.0f / 15.0f) * (float)(2 * q + 1);
                float z0 = (Dp - mu0) * 0.8f, z1 = (Dp - mu1) * 0.8f;
                w[q] = packh2(__expf(-z0 * z0), __expf(-z1 * z1));
            }
            An[(row * ASTR + cb) >> 2]     = make_uint4(w[0], w[1], w[2], w[3]);
            An[(row * ASTR + cb + 4) >> 2] = make_uint4(w[4], w[5], w[6], w[7]);
        }
    }

    // ---- epilogue: per-row partials across the 4 colgroup warps ----
#pragma unroll
    for (int rt = 0; rt < 3; rt++) {
        float s0 = 0.f, q0 = 0.f, s1 = 0.f, q1 = 0.f;
#pragma unroll
        for (int j = 0; j < 4; j++) {
            s0 += acc[rt][j][0] + acc[rt][j][1];
            q0 += acc[rt][j][0] * acc[rt][j][0] + acc[rt][j][1] * acc[rt][j][1];
            s1 += acc[rt][j][2] + acc[rt][j][3];
            q1 += acc[rt][j][2] * acc[rt][j][2] + acc[rt][j][3] * acc[rt][j][3];
        }
#pragma unroll
        for (int m = 1; m <= 2; m <<= 1) {
            s0 += __shfl_xor_sync(0xffffffffu, s0, m);
            q0 += __shfl_xor_sync(0xffffffffu, q0, m);
            s1 += __shfl_xor_sync(0xffffffffu, s1, m);
            q1 += __shfl_xor_sync(0xffffffffu, q1, m);
        }
        if (tg == 0) {
            int r0 = rowbase + rt * 16 + gid;
            psum[r0][cg]     = make_float2(s0, q0);
            psum[r0 + 8][cg] = make_float2(s1, q1);
        }
    }
    __syncthreads();

    // ---- LN in registers + direct float2 stores to gmem ----
    size_t obase = (size_t)node0 * KNN * ED;
#pragma unroll
    for (int rt = 0; rt < 3; rt++) {
        int r0 = rowbase + rt * 16 + gid;
        float2 pa0 = psum[r0][0], pa1 = psum[r0][1];
        float2 pa2 = psum[r0][2], pa3 = psum[r0][3];
        float2 pb0 = psum[r0 + 8][0], pb1 = psum[r0 + 8][1];
        float2 pb2 = psum[r0 + 8][2], pb3 = psum[r0 + 8][3];
        float mean0 = (pa0.x + pa1.x + pa2.x + pa3.x) * (1.0f / 128.0f);
        float var0  = (pa0.y + pa1.y + pa2.y + pa3.y) * (1.0f / 128.0f) - mean0 * mean0;
        float rs0   = rsqrtf(var0 + 1e-5f);
        float mean1 = (pb0.x + pb1.x + pb2.x + pb3.x) * (1.0f / 128.0f);
        float var1  = (pb0.y + pb1.y + pb2.y + pb3.y) * (1.0f / 128.0f) - mean1 * mean1;
        float rs1   = rsqrtf(var1 + 1e-5f);
        float* dst0 = outE + obase + (size_t)r0 * ED;
        float* dst1 = dst0 + 8 * ED;
#pragma unroll
        for (int j = 0; j < 4; j++) {
            int col = colbase + j * 8 + 2 * tg;
            float g0 = gam[col], g1 = gam[col + 1];
            float b0 = bet[col], b1 = bet[col + 1];
            *(float2*)(dst0 + col) =
                make_float2((acc[rt][j][0] - mean0) * rs0 * g0 + b0,
                            (acc[rt][j][1] - mean0) * rs0 * g1 + b1);
            *(float2*)(dst1 + col) =
                make_float2((acc[rt][j][2] - mean1) * rs1 * g0 + b0,
                            (acc[rt][j][3] - mean1) * rs1 * g1 + b1);
        }
    }
}

// ---------------------------------------------------------------------------
// Launch: two-pipeline fork/join. Default stream: topk rows [0,2048) then
// edge pairs [0,1024). Fork stream s1 (event after prep): topk rows
// [2048,4096) then edge pairs [1024,2048). Event-join back to default.
// Stream/event creation is host-side (kernel_launch runs only a few times;
// graph replays don't re-run host code). No device allocations.
// ---------------------------------------------------------------------------
extern "C" void kernel_launch(void* const* d_in, const int* in_sizes, int n_in,
                              void* d_out, int out_size) {
    const float* X     = (const float*)d_in[0];
    const float* mask  = (const float*)d_in[1];
    const int*   ridx  = (const int*)d_in[2];
    const int*   chain = (const int*)d_in[3];
    const float* Wpos  = (const float*)d_in[4];
    const float* bpos  = (const float*)d_in[5];
    const float* Wedge = (const float*)d_in[6];
    const float* gam   = (const float*)d_in[7];
    const float* bet   = (const float*)d_in[8];

    float* outE = (float*)d_out;
    size_t nE = (size_t)BB * LL * KNN * ED;
    float* outI = ((size_t)out_size > nE) ? (outE + nE) : nullptr;

    static const int smemK3 = DSMW * 4;   // 49152 B (pipeline only)
    cudaFuncSetAttribute(edge_kernel,
                         cudaFuncAttributeMaxDynamicSharedMemorySize, smemK3);

    cudaStream_t s1 = 0;
    cudaEvent_t evFork = 0, evJoin = 0;
    bool forked =
        (cudaStreamCreateWithFlags(&s1, cudaStreamNonBlocking) == cudaSuccess) &&
        (cudaEventCreateWithFlags(&evFork, cudaEventDisableTiming) == cudaSuccess) &&
        (cudaEventCreateWithFlags(&evJoin, cudaEventDisableTiming) == cudaSuccess);

    prep_kernel<<<16 + (208 * ED + 255) / 256, 256>>>(X, mask, Wedge);

    if (forked) {
        cudaEventRecord(evFork, 0);
        cudaStreamWaitEvent(s1, evFork, 0);

        topk_kernel<<<BB * LL / 2, 256>>>(outI, 0);
        topk_kernel<<<BB * LL / 2, 256, 0, s1>>>(outI, BB * LL / 2);

        edge_kernel<<<BB * LL / 4, 256, smemK3>>>(ridx, chain, Wpos, bpos,
                                                  gam, bet, outE, 0);
        edge_kernel<<<BB * LL / 4, 256, smemK3, s1>>>(ridx, chain, Wpos, bpos,
                                                      gam, bet, outE,
                                                      BB * LL / 4);

        cudaEventRecord(evJoin, s1);
        cudaStreamWaitEvent(0, evJoin, 0);
        // handles are not destroyed here: the fork stream is still part of
        // the active capture; a few leaked host-side handles are harmless.
    } else {
        topk_kernel<<<BB * LL / 2, 256>>>(outI, 0);
        topk_kernel<<<BB * LL / 2, 256>>>(outI, BB * LL / 2);
        edge_kernel<<<BB * LL / 4, 256, smemK3>>>(ridx, chain, Wpos, bpos,
                                                  gam, bet, outE, 0);
        edge_kernel<<<BB * LL / 4, 256, smemK3>>>(ridx, chain, Wpos, bpos,
                                                  gam, bet, outE, BB * LL / 4);
    }
    (void)in_sizes; (void)n_in;
}